// round 2
// baseline (speedup 1.0000x reference)
#include <cuda_runtime.h>
#include <cstdint>

// Scratch for Q/K/V projections: [2048, 1024] each (row i, col h*64+d)
__device__ float g_Q[2048 * 1024];
__device__ float g_K[2048 * 1024];
__device__ float g_V[2048 * 1024];

// ---------------------------------------------------------------------------
// Kernel 1: QKV projection GEMM.  C = X @ W + b for W in {Wq,Wk,Wv} (z-dim).
// Tile: 128x64, BK=16, 256 threads (16x16), 8x4 per-thread micro-tile.
// ---------------------------------------------------------------------------
__global__ __launch_bounds__(256, 4)
void qkv_gemm_kernel(const float* __restrict__ X,
                     const float* __restrict__ Wq, const float* __restrict__ bq,
                     const float* __restrict__ Wk, const float* __restrict__ bk,
                     const float* __restrict__ Wv, const float* __restrict__ bv)
{
    __shared__ float As[16][128];   // [k][m]  (X tile, transposed)
    __shared__ float Bs[16][64];    // [k][n]  (W tile)

    const float* W; const float* bias; float* C;
    if (blockIdx.z == 0)      { W = Wq; bias = bq; C = g_Q; }
    else if (blockIdx.z == 1) { W = Wk; bias = bk; C = g_K; }
    else                      { W = Wv; bias = bv; C = g_V; }

    const int tid = threadIdx.x;
    const int tx = tid & 15, ty = tid >> 4;
    const int m0 = blockIdx.y * 128, n0 = blockIdx.x * 64;

    float acc[8][4];
#pragma unroll
    for (int r = 0; r < 8; ++r)
#pragma unroll
        for (int c = 0; c < 4; ++c) acc[r][c] = 0.f;

    for (int k0 = 0; k0 < 1024; k0 += 16) {
        // Load X tile 128x16 (2 float4 per thread), store transposed
#pragma unroll
        for (int l = tid; l < 512; l += 256) {
            int row = l >> 2, kk = (l & 3) << 2;
            float4 v = *(const float4*)(X + (size_t)(m0 + row) * 1024 + k0 + kk);
            As[kk + 0][row] = v.x; As[kk + 1][row] = v.y;
            As[kk + 2][row] = v.z; As[kk + 3][row] = v.w;
        }
        // Load W tile 16x64 (1 float4 per thread)
        {
            int row = tid >> 4, c4 = (tid & 15) << 2;
            *(float4*)&Bs[row][c4] =
                *(const float4*)(W + (size_t)(k0 + row) * 1024 + n0 + c4);
        }
        __syncthreads();

#pragma unroll
        for (int k = 0; k < 16; ++k) {
            float4 b  = *(float4*)&Bs[k][tx << 2];
            float4 a0 = *(float4*)&As[k][ty << 3];
            float4 a1 = *(float4*)&As[k][(ty << 3) + 4];
            float ar[8] = {a0.x, a0.y, a0.z, a0.w, a1.x, a1.y, a1.z, a1.w};
#pragma unroll
            for (int r = 0; r < 8; ++r) {
                acc[r][0] += ar[r] * b.x;
                acc[r][1] += ar[r] * b.y;
                acc[r][2] += ar[r] * b.z;
                acc[r][3] += ar[r] * b.w;
            }
        }
        __syncthreads();
    }

    float4 bb = *(const float4*)(bias + n0 + (tx << 2));
#pragma unroll
    for (int r = 0; r < 8; ++r) {
        int row = m0 + (ty << 3) + r;
        float4 o;
        o.x = acc[r][0] + bb.x; o.y = acc[r][1] + bb.y;
        o.z = acc[r][2] + bb.z; o.w = acc[r][3] + bb.w;
        *(float4*)(C + (size_t)row * 1024 + n0 + (tx << 2)) = o;
    }
}

// ---------------------------------------------------------------------------
// Kernel 2: flash-style attention per (query-tile 64, head).
//   - a_k = Q_tile @ W_rel_k computed once per block (bias term, pre-scale)
//   - online softmax (64x64 key tiles), mask applied as (1-m)*FLT_MIN
//   - rel_v band folded into PV accumulation for the 3 diagonal tiles
// Dynamic smem = 103424 bytes.
// ---------------------------------------------------------------------------
#define ATTN_SMEM_FLOATS 25856  /* 4352+4352+8448+8448+64+192 */

__global__ __launch_bounds__(256, 2)
void attn_kernel(const float* __restrict__ mask,
                 const float* __restrict__ Wrk,   // [64][129]
                 const float* __restrict__ Wrv,   // [129][64]
                 float* __restrict__ out)
{
    extern __shared__ float sm[];
    float* Qs   = sm;            // [64][68]
    float* Ps   = sm + 4352;     // [64][68]
    float* ak   = sm + 8704;     // [64][132]
    float* KVu  = sm + 17152;    // union: Wrk staging [64][132] OR Kts[64][64]+Vs[64][64]
    float* ms   = sm + 25600;    // [64]
    float* mrow = sm + 25664;    // [64]
    float* lrow = sm + 25728;    // [64]
    float* frow = sm + 25792;    // [64]

    const int tid = threadIdx.x;
    const int tx = tid & 15, ty = tid >> 4;
    const int h  = blockIdx.y;
    const int i0 = blockIdx.x * 64;
    const int hc = h * 64;

    // ---- Load Q tile (rows i0..i0+63, cols h*64..h*64+63) ----
#pragma unroll
    for (int l = tid; l < 1024; l += 256) {
        int row = l >> 4, c4 = (l & 15) << 2;
        float4 v = *(const float4*)(g_Q + (size_t)(i0 + row) * 1024 + hc + c4);
        *(float4*)(Qs + row * 68 + c4) = v;
    }
    // ---- Stage W_rel_k [64][129] into KVu [64][132], zero pad cols 129..131 ----
    for (int l = tid; l < 64 * 129; l += 256) {
        int d = l / 129, w = l - d * 129;
        KVu[d * 132 + w] = Wrk[l];
    }
    if (tid < 192) { int d = tid / 3, c = 129 + (tid % 3); KVu[d * 132 + c] = 0.f; }
    if (tid < 64)  { mrow[tid] = -1e30f; lrow[tid] = 0.f; }
    __syncthreads();

    // ---- a_k[i][w] = sum_d Qs[i][d] * Wrk[d][w]  (4 w's per thread) ----
    for (int idx = tid; idx < 64 * 33; idx += 256) {
        int i = idx / 33, w4 = idx - i * 33;
        int w = w4 << 2;
        float s0 = 0.f, s1 = 0.f, s2 = 0.f, s3 = 0.f;
        const float* qrow = Qs + i * 68;
#pragma unroll 8
        for (int d = 0; d < 64; ++d) {
            float a = qrow[d];
            float4 bw = *(const float4*)(KVu + d * 132 + w);
            s0 += a * bw.x; s1 += a * bw.y; s2 += a * bw.z; s3 += a * bw.w;
        }
        if (w < 128) {
            float4 o; o.x = s0; o.y = s1; o.z = s2; o.w = s3;
            *(float4*)(ak + i * 132 + w) = o;
        } else {
            ak[i * 132 + 128] = s0;
        }
    }
    __syncthreads();

    float* Kts = KVu;            // [d][j] = [64][64]
    float* Vs  = KVu + 4096;     // [j][d] = [64][64]

    float acc[4][4];
#pragma unroll
    for (int r = 0; r < 4; ++r)
#pragma unroll
        for (int c = 0; c < 4; ++c) acc[r][c] = 0.f;

    for (int jt = 0; jt < 32; ++jt) {
        const int j0 = jt * 64;
        // ---- load K tile transposed [d][j] + V tile [j][d] + mask slice ----
#pragma unroll
        for (int l = tid; l < 1024; l += 256) {
            int j = l >> 4, d4 = (l & 15) << 2;
            float4 v = *(const float4*)(g_K + (size_t)(j0 + j) * 1024 + hc + d4);
            Kts[(d4 + 0) * 64 + j] = v.x; Kts[(d4 + 1) * 64 + j] = v.y;
            Kts[(d4 + 2) * 64 + j] = v.z; Kts[(d4 + 3) * 64 + j] = v.w;
        }
#pragma unroll
        for (int l = tid; l < 1024; l += 256) {
            int j = l >> 4, d4 = (l & 15) << 2;
            *(float4*)(Vs + j * 64 + d4) =
                *(const float4*)(g_V + (size_t)(j0 + j) * 1024 + hc + d4);
        }
        if (tid < 64) ms[tid] = mask[j0 + tid];
        __syncthreads();

        // ---- S = Q @ K^T  (each thread: 4x4) ----
        float sa[4][4];
#pragma unroll
        for (int r = 0; r < 4; ++r)
#pragma unroll
            for (int c = 0; c < 4; ++c) sa[r][c] = 0.f;

#pragma unroll 8
        for (int d = 0; d < 64; ++d) {
            float4 b = *(float4*)(Kts + d * 64 + (tx << 2));
            float a0 = Qs[(ty * 4 + 0) * 68 + d];
            float a1 = Qs[(ty * 4 + 1) * 68 + d];
            float a2 = Qs[(ty * 4 + 2) * 68 + d];
            float a3 = Qs[(ty * 4 + 3) * 68 + d];
            sa[0][0] += a0 * b.x; sa[0][1] += a0 * b.y; sa[0][2] += a0 * b.z; sa[0][3] += a0 * b.w;
            sa[1][0] += a1 * b.x; sa[1][1] += a1 * b.y; sa[1][2] += a1 * b.z; sa[1][3] += a1 * b.w;
            sa[2][0] += a2 * b.x; sa[2][1] += a2 * b.y; sa[2][2] += a2 * b.z; sa[2][3] += a2 * b.w;
            sa[3][0] += a3 * b.x; sa[3][1] += a3 * b.y; sa[3][2] += a3 * b.z; sa[3][3] += a3 * b.w;
        }

        // ---- bias (pre-scale) + scale + mask → Ps ----
        const int delta = j0 - i0 + 64;
#pragma unroll
        for (int r = 0; r < 4; ++r) {
            int il = ty * 4 + r;
#pragma unroll
            for (int c = 0; c < 4; ++c) {
                int jl = tx * 4 + c;
                float s = sa[r][c];
                int slot = delta + jl - il;
                if (slot >= 0 && slot <= 128) s += ak[il * 132 + slot];
                s = s * 0.125f + (1.0f - ms[jl]) * (-3.4028235e38f);
                Ps[il * 68 + jl] = s;
            }
        }
        __syncthreads();

        // ---- online softmax update: 4 threads per row ----
        {
            int row = tid >> 2, l4 = tid & 3;
            float* pr = Ps + row * 68;
            float mx = -1e30f;
            for (int c = l4; c < 64; c += 4) mx = fmaxf(mx, pr[c]);
            mx = fmaxf(mx, __shfl_xor_sync(0xffffffffu, mx, 1));
            mx = fmaxf(mx, __shfl_xor_sync(0xffffffffu, mx, 2));
            float m_old = mrow[row];
            float m_new = fmaxf(m_old, mx);
            float sum = 0.f;
            for (int c = l4; c < 64; c += 4) {
                float p = __expf(pr[c] - m_new);
                pr[c] = p;
                sum += p;
            }
            sum += __shfl_xor_sync(0xffffffffu, sum, 1);
            sum += __shfl_xor_sync(0xffffffffu, sum, 2);
            if (l4 == 0) {
                float f = __expf(m_old - m_new);
                frow[row] = f;
                lrow[row] = lrow[row] * f + sum;
                mrow[row] = m_new;
            }
        }
        __syncthreads();

        // ---- rescale accumulators ----
        float fr[4];
#pragma unroll
        for (int r = 0; r < 4; ++r) fr[r] = frow[ty * 4 + r];
#pragma unroll
        for (int r = 0; r < 4; ++r)
#pragma unroll
            for (int c = 0; c < 4; ++c) acc[r][c] *= fr[r];

        // ---- PV accumulation (+ folded rel_v band for diagonal tiles) ----
        const bool band = (delta >= 0 && delta <= 128);
#pragma unroll 4
        for (int j = 0; j < 64; ++j) {
            float p[4];
            p[0] = Ps[(ty * 4 + 0) * 68 + j];
            p[1] = Ps[(ty * 4 + 1) * 68 + j];
            p[2] = Ps[(ty * 4 + 2) * 68 + j];
            p[3] = Ps[(ty * 4 + 3) * 68 + j];
            float4 v = *(float4*)(Vs + j * 64 + (tx << 2));
#pragma unroll
            for (int r = 0; r < 4; ++r) {
                acc[r][0] += p[r] * v.x; acc[r][1] += p[r] * v.y;
                acc[r][2] += p[r] * v.z; acc[r][3] += p[r] * v.w;
            }
            if (band) {
#pragma unroll
                for (int r = 0; r < 4; ++r) {
                    int w = delta + j - (ty * 4 + r);
                    if (w >= 0 && w <= 128) {
                        float4 wv = *(const float4*)(Wrv + w * 64 + (tx << 2));
                        acc[r][0] += p[r] * wv.x; acc[r][1] += p[r] * wv.y;
                        acc[r][2] += p[r] * wv.z; acc[r][3] += p[r] * wv.w;
                    }
                }
            }
        }
        __syncthreads();
    }

    // ---- epilogue: normalize by l, write out[n][h*64+d] ----
#pragma unroll
    for (int r = 0; r < 4; ++r) {
        int row = ty * 4 + r;
        float inv = 1.0f / lrow[row];
        float4 o;
        o.x = acc[r][0] * inv; o.y = acc[r][1] * inv;
        o.z = acc[r][2] * inv; o.w = acc[r][3] * inv;
        *(float4*)(out + (size_t)(i0 + row) * 1024 + hc + (tx << 2)) = o;
    }
}

// ---------------------------------------------------------------------------
extern "C" void kernel_launch(void* const* d_in, const int* in_sizes, int n_in,
                              void* d_out, int out_size)
{
    const float* X   = (const float*)d_in[0];
    const float* msk = (const float*)d_in[1];
    const float* Wq  = (const float*)d_in[2];
    const float* bq  = (const float*)d_in[3];
    const float* Wk  = (const float*)d_in[4];
    const float* bk  = (const float*)d_in[5];
    const float* Wv  = (const float*)d_in[6];
    const float* bv  = (const float*)d_in[7];
    const float* Wrk = (const float*)d_in[8];
    const float* Wrv = (const float*)d_in[9];
    float* out = (float*)d_out;

    cudaFuncSetAttribute(attn_kernel,
                         cudaFuncAttributeMaxDynamicSharedMemorySize,
                         ATTN_SMEM_FLOATS * 4);

    dim3 gGemm(16, 16, 3);   // 1024/64 n-tiles, 2048/128 m-tiles, {Q,K,V}
    qkv_gemm_kernel<<<gGemm, 256>>>(X, Wq, bq, Wk, bk, Wv, bv);

    dim3 gAttn(32, 16);      // 2048/64 query tiles, 16 heads
    attn_kernel<<<gAttn, 256, ATTN_SMEM_FLOATS * 4>>>(msk, Wrk, Wrv, out);
}

// round 4
// speedup vs baseline: 1.4863x; 1.4863x over previous
#include <cuda_runtime.h>
#include <cuda_bf16.h>
#include <cstdint>

__device__ float g_Q[2048 * 1024];
__device__ float g_K[2048 * 1024];
__device__ float g_V[2048 * 1024];

// ---------------- smem layout (bytes) for attention kernel ----------------
#define OFF_QH   0        /* [128][72] bf16, row stride 144B  */
#define OFF_QL   18432
#define OFF_KH   36864    /* [64][72] bf16                    */
#define OFF_KL   46080
#define OFF_VTH  55296    /* [64][72] bf16 (V transposed d,j) */
#define OFF_VTL  64512
#define OFF_AK   73728    /* bf16 [128][132]                  */
#define OFF_BAND 107520   /* bf16 [128][136]                  */
#define OFF_WRVT 142336   /* bf16 [64][136]                   */
#define OFF_MS   159744   /* 64 floats                        */
#define ATT_SMEM 160000

// ---------------- helpers ----------------
__device__ __forceinline__ void mma16816(float* c, const uint32_t* a,
                                         uint32_t b0, uint32_t b1) {
    asm volatile(
        "mma.sync.aligned.m16n8k16.row.col.f32.bf16.bf16.f32 "
        "{%0,%1,%2,%3}, {%4,%5,%6,%7}, {%8,%9}, {%0,%1,%2,%3};"
        : "+f"(c[0]), "+f"(c[1]), "+f"(c[2]), "+f"(c[3])
        : "r"(a[0]), "r"(a[1]), "r"(a[2]), "r"(a[3]), "r"(b0), "r"(b1));
}
// split (x,y) into packed hi-bf16 pair and lo-bf16 (residual) pair
__device__ __forceinline__ void split2u(float x, float y, uint32_t& h, uint32_t& l) {
    __nv_bfloat16 hx = __float2bfloat16(x), hy = __float2bfloat16(y);
    h = ((uint32_t)__bfloat16_as_ushort(hy) << 16) | __bfloat16_as_ushort(hx);
    __nv_bfloat16 lx = __float2bfloat16(x - __bfloat162float(hx));
    __nv_bfloat16 ly = __float2bfloat16(y - __bfloat162float(hy));
    l = ((uint32_t)__bfloat16_as_ushort(ly) << 16) | __bfloat16_as_ushort(lx);
}

// ---------------------------------------------------------------------------
// Kernel 1: SIMT QKV projection GEMM (unchanged from R1, known-good, ~335us)
// ---------------------------------------------------------------------------
__global__ __launch_bounds__(256, 4)
void qkv_gemm_kernel(const float* __restrict__ X,
                     const float* __restrict__ Wq, const float* __restrict__ bq,
                     const float* __restrict__ Wk, const float* __restrict__ bk,
                     const float* __restrict__ Wv, const float* __restrict__ bv)
{
    __shared__ float As[16][128];
    __shared__ float Bs[16][64];
    const float* W; const float* bias; float* C;
    if (blockIdx.z == 0)      { W = Wq; bias = bq; C = g_Q; }
    else if (blockIdx.z == 1) { W = Wk; bias = bk; C = g_K; }
    else                      { W = Wv; bias = bv; C = g_V; }
    const int tid = threadIdx.x, tx = tid & 15, ty = tid >> 4;
    const int m0 = blockIdx.y * 128, n0 = blockIdx.x * 64;
    float acc[8][4];
#pragma unroll
    for (int r = 0; r < 8; ++r)
#pragma unroll
        for (int c = 0; c < 4; ++c) acc[r][c] = 0.f;
    for (int k0 = 0; k0 < 1024; k0 += 16) {
#pragma unroll
        for (int l = tid; l < 512; l += 256) {
            int row = l >> 2, kk = (l & 3) << 2;
            float4 v = *(const float4*)(X + (size_t)(m0 + row) * 1024 + k0 + kk);
            As[kk][row] = v.x; As[kk + 1][row] = v.y;
            As[kk + 2][row] = v.z; As[kk + 3][row] = v.w;
        }
        {
            int row = tid >> 4, c4 = (tid & 15) << 2;
            *(float4*)&Bs[row][c4] = *(const float4*)(W + (size_t)(k0 + row) * 1024 + n0 + c4);
        }
        __syncthreads();
#pragma unroll
        for (int k = 0; k < 16; ++k) {
            float4 b = *(float4*)&Bs[k][tx << 2];
            float4 a0 = *(float4*)&As[k][ty << 3];
            float4 a1 = *(float4*)&As[k][(ty << 3) + 4];
            float ar[8] = {a0.x, a0.y, a0.z, a0.w, a1.x, a1.y, a1.z, a1.w};
#pragma unroll
            for (int r = 0; r < 8; ++r) {
                acc[r][0] += ar[r] * b.x; acc[r][1] += ar[r] * b.y;
                acc[r][2] += ar[r] * b.z; acc[r][3] += ar[r] * b.w;
            }
        }
        __syncthreads();
    }
    float4 bb = *(const float4*)(bias + n0 + (tx << 2));
#pragma unroll
    for (int r = 0; r < 8; ++r) {
        int row = m0 + (ty << 3) + r;
        float4 o;
        o.x = acc[r][0] + bb.x; o.y = acc[r][1] + bb.y;
        o.z = acc[r][2] + bb.z; o.w = acc[r][3] + bb.w;
        *(float4*)(C + (size_t)row * 1024 + n0 + (tx << 2)) = o;
    }
}

// ---------------------------------------------------------------------------
// Kernel 2: mma.sync (HMMA) flash attention.
// Block = (i-tile of 128 rows, head). 256 threads = 8 warps x 16 rows.
// 3-term bf16 split emulation for S = QK^T and ctx = P V.
// ---------------------------------------------------------------------------
__global__ __launch_bounds__(256, 1)
void attn_mma_kernel(const float* __restrict__ mask,
                     const float* __restrict__ Wrk,   // [64][129]
                     const float* __restrict__ Wrv,   // [129][64]
                     float* __restrict__ out)
{
    extern __shared__ __align__(16) char sm[];
    const int tid  = threadIdx.x;
    const int warp = tid >> 5, lane = tid & 31;
    const int tq = lane >> 2, tr = lane & 3;
    const int lr = warp * 16 + tq;          // local rows lr, lr+8
    const int i0 = blockIdx.x * 128, hc = blockIdx.y * 64;

    __nv_bfloat16* AK = (__nv_bfloat16*)(sm + OFF_AK);
    float* MS = (float*)(sm + OFF_MS);

    // ---- stage Q hi/lo [128][72] ----
    for (int l = tid; l < 2048; l += 256) {
        int r = l >> 4, dq = (l & 15) << 2;
        float4 v = *(const float4*)(g_Q + (size_t)(i0 + r) * 1024 + hc + dq);
        uint32_t h0, l0, h1, l1;
        split2u(v.x, v.y, h0, l0); split2u(v.z, v.w, h1, l1);
        uint2 H = {h0, h1}, L = {l0, l1};
        *(uint2*)(sm + OFF_QH + r * 144 + dq * 2) = H;
        *(uint2*)(sm + OFF_QL + r * 144 + dq * 2) = L;
    }
    // ---- stage WrkT (hi only): KH = w 0..63, KL = w 64..127, layout [w][72] ----
    for (int l = tid; l < 1024; l += 256) {
        int w = l >> 4, dg = (l & 15) << 2;
        uint32_t a0, a1, b0, b1;
        {
            float x0 = Wrk[(dg + 0) * 129 + w],     x1 = Wrk[(dg + 1) * 129 + w];
            float x2 = Wrk[(dg + 2) * 129 + w],     x3 = Wrk[(dg + 3) * 129 + w];
            float y0 = Wrk[(dg + 0) * 129 + w + 64], y1 = Wrk[(dg + 1) * 129 + w + 64];
            float y2 = Wrk[(dg + 2) * 129 + w + 64], y3 = Wrk[(dg + 3) * 129 + w + 64];
            uint32_t t;
            split2u(x0, x1, a0, t); split2u(x2, x3, a1, t);
            split2u(y0, y1, b0, t); split2u(y2, y3, b1, t);
        }
        uint2 A = {a0, a1}, B = {b0, b1};
        *(uint2*)(sm + OFF_KH + w * 144 + dg * 2) = A;
        *(uint2*)(sm + OFF_KL + w * 144 + dg * 2) = B;
    }
    // ---- zero band ----
    for (int l = tid; l < 8704; l += 256) ((uint32_t*)(sm + OFF_BAND))[l] = 0;
    // ---- edge bias column ak[:,128] (SIMT fp32) ----
    if (tid < 128) {
        float s = 0.f;
        const float* qr = g_Q + (size_t)(i0 + tid) * 1024 + hc;
#pragma unroll 8
        for (int d = 0; d < 64; ++d) s += qr[d] * Wrk[d * 129 + 128];
        AK[tid * 132 + 128] = __float2bfloat16(s);
    }
    __syncthreads();

    // ---- Q fragments (registers, reused all tiles) ----
    uint32_t qh[4][4], ql[4][4];
#pragma unroll
    for (int kc = 0; kc < 4; ++kc) {
        int cb = (kc * 16 + tr * 2) * 2;
        qh[kc][0] = *(uint32_t*)(sm + OFF_QH + lr * 144 + cb);
        qh[kc][1] = *(uint32_t*)(sm + OFF_QH + (lr + 8) * 144 + cb);
        qh[kc][2] = *(uint32_t*)(sm + OFF_QH + lr * 144 + cb + 16);
        qh[kc][3] = *(uint32_t*)(sm + OFF_QH + (lr + 8) * 144 + cb + 16);
        ql[kc][0] = *(uint32_t*)(sm + OFF_QL + lr * 144 + cb);
        ql[kc][1] = *(uint32_t*)(sm + OFF_QL + (lr + 8) * 144 + cb);
        ql[kc][2] = *(uint32_t*)(sm + OFF_QL + lr * 144 + cb + 16);
        ql[kc][3] = *(uint32_t*)(sm + OFF_QL + (lr + 8) * 144 + cb + 16);
    }

    // ---- ak = Q @ WrkT^T via MMA (hi only), write bf16 table ----
#pragma unroll
    for (int half = 0; half < 2; ++half) {
        int KO = half ? OFF_KL : OFF_KH;
#pragma unroll
        for (int nc = 0; nc < 8; ++nc) {
            float c[4] = {0.f, 0.f, 0.f, 0.f};
#pragma unroll
            for (int kc = 0; kc < 4; ++kc) {
                int base = KO + (nc * 8 + tq) * 144 + (kc * 16 + tr * 2) * 2;
                uint32_t b0 = *(uint32_t*)(sm + base);
                uint32_t b1 = *(uint32_t*)(sm + base + 16);
                mma16816(c, qh[kc], b0, b1);
            }
            int w = half * 64 + nc * 8 + tr * 2;
            AK[lr * 132 + w]           = __float2bfloat16(c[0]);
            AK[lr * 132 + w + 1]       = __float2bfloat16(c[1]);
            AK[(lr + 8) * 132 + w]     = __float2bfloat16(c[2]);
            AK[(lr + 8) * 132 + w + 1] = __float2bfloat16(c[3]);
        }
    }
    __syncthreads();

    float ctx[8][4];
#pragma unroll
    for (int nc = 0; nc < 8; ++nc)
#pragma unroll
        for (int q = 0; q < 4; ++q) ctx[nc][q] = 0.f;
    float rs0 = 0.f, rs1 = 0.f, pe0 = 0.f, pe1 = 0.f;

    for (int jt = 0; jt < 32; ++jt) {
        const int j0 = jt * 64;
        // ---- stage K hi/lo [64][72] ----
        for (int l = tid; l < 1024; l += 256) {
            int r = l >> 4, dq = (l & 15) << 2;
            float4 v = *(const float4*)(g_K + (size_t)(j0 + r) * 1024 + hc + dq);
            uint32_t h0, l0, h1, l1;
            split2u(v.x, v.y, h0, l0); split2u(v.z, v.w, h1, l1);
            uint2 H = {h0, h1}, L = {l0, l1};
            *(uint2*)(sm + OFF_KH + r * 144 + dq * 2) = H;
            *(uint2*)(sm + OFF_KL + r * 144 + dq * 2) = L;
        }
        // ---- stage V transposed hi/lo: VT[d][j], [64][72] ----
        for (int l = tid; l < 1024; l += 256) {
            int j = l >> 4, dq = (l & 15) << 2;
            float4 v = *(const float4*)(g_V + (size_t)(j0 + j) * 1024 + hc + dq);
            float f[4] = {v.x, v.y, v.z, v.w};
#pragma unroll
            for (int q = 0; q < 4; ++q) {
                __nv_bfloat16 hb = __float2bfloat16(f[q]);
                __nv_bfloat16 lb = __float2bfloat16(f[q] - __bfloat162float(hb));
                *(__nv_bfloat16*)(sm + OFF_VTH + (dq + q) * 144 + j * 2) = hb;
                *(__nv_bfloat16*)(sm + OFF_VTL + (dq + q) * 144 + j * 2) = lb;
            }
        }
        if (tid < 64) MS[tid] = mask[j0 + tid];
        __syncthreads();

        // ---- S = Q K^T (3-term split) ----
        float c[8][4];
#pragma unroll
        for (int nc = 0; nc < 8; ++nc)
#pragma unroll
            for (int q = 0; q < 4; ++q) c[nc][q] = 0.f;
#pragma unroll
        for (int kc = 0; kc < 4; ++kc) {
#pragma unroll
            for (int nc = 0; nc < 8; ++nc) {
                int base = (nc * 8 + tq) * 144 + (kc * 16 + tr * 2) * 2;
                uint32_t bh0 = *(uint32_t*)(sm + OFF_KH + base);
                uint32_t bh1 = *(uint32_t*)(sm + OFF_KH + base + 16);
                uint32_t bl0 = *(uint32_t*)(sm + OFF_KL + base);
                uint32_t bl1 = *(uint32_t*)(sm + OFF_KL + base + 16);
                mma16816(c[nc], qh[kc], bh0, bh1);
                mma16816(c[nc], qh[kc], bl0, bl1);
                mma16816(c[nc], ql[kc], bh0, bh1);
            }
        }

        // ---- epilogue: bias + scale + mask + exp ; band scatter ----
        const int sb0 = j0 - i0 + 64;
        const bool doBand = (sb0 >= -63 && sb0 <= 255);
#pragma unroll
        for (int nc = 0; nc < 8; ++nc) {
#pragma unroll
            for (int idx = 0; idx < 4; ++idx) {
                int lrr = lr + ((idx >> 1) << 3);
                int col = nc * 8 + tr * 2 + (idx & 1);
                float s = c[nc][idx];
                int w = sb0 + col - lrr;
                if (doBand && w >= 0 && w <= 128)
                    s += __bfloat162float(AK[lrr * 132 + w]);
                s = s * 0.125f + (1.0f - MS[col]) * (-3.4028235e38f);
                float e = __expf(s);
                if (idx < 2) rs0 += e; else rs1 += e;
                if (doBand) {
                    if (w >= 0 && w < 128)
                        *(__nv_bfloat16*)(sm + OFF_BAND + lrr * 272 + w * 2) =
                            __float2bfloat16(e);
                    else if (w == 128) { if (idx < 2) pe0 = e; else pe1 = e; }
                }
                c[nc][idx] = e;
            }
        }

        // ---- repack P as A-fragments (hi/lo) ----
        uint32_t ph[4][4], pl[4][4];
#pragma unroll
        for (int kc = 0; kc < 4; ++kc) {
            split2u(c[2 * kc][0],     c[2 * kc][1],     ph[kc][0], pl[kc][0]);
            split2u(c[2 * kc][2],     c[2 * kc][3],     ph[kc][1], pl[kc][1]);
            split2u(c[2 * kc + 1][0], c[2 * kc + 1][1], ph[kc][2], pl[kc][2]);
            split2u(c[2 * kc + 1][2], c[2 * kc + 1][3], ph[kc][3], pl[kc][3]);
        }

        // ---- ctx += P V (3-term split) ----
#pragma unroll
        for (int kc = 0; kc < 4; ++kc) {
#pragma unroll
            for (int nc = 0; nc < 8; ++nc) {
                int base = (nc * 8 + tq) * 144 + (kc * 16 + tr * 2) * 2;
                uint32_t vh0 = *(uint32_t*)(sm + OFF_VTH + base);
                uint32_t vh1 = *(uint32_t*)(sm + OFF_VTH + base + 16);
                uint32_t vl0 = *(uint32_t*)(sm + OFF_VTL + base);
                uint32_t vl1 = *(uint32_t*)(sm + OFF_VTL + base + 16);
                mma16816(ctx[nc], ph[kc], vh0, vh1);
                mma16816(ctx[nc], ph[kc], vl0, vl1);
                mma16816(ctx[nc], pl[kc], vh0, vh1);
            }
        }
        __syncthreads();
    }

    // ---- stage WrvT [d][136] (hi only) ----
    for (int l = tid; l < 8192; l += 256) {
        int d = l >> 7, w = l & 127;
        *(__nv_bfloat16*)(sm + OFF_WRVT + d * 272 + w * 2) =
            __float2bfloat16(Wrv[w * 64 + d]);
    }
    __syncthreads();

    // ---- ctx += band @ WrvT^T ----
#pragma unroll
    for (int kc = 0; kc < 8; ++kc) {
        int cb = (kc * 16 + tr * 2) * 2;
        uint32_t af[4];
        af[0] = *(uint32_t*)(sm + OFF_BAND + lr * 272 + cb);
        af[1] = *(uint32_t*)(sm + OFF_BAND + (lr + 8) * 272 + cb);
        af[2] = *(uint32_t*)(sm + OFF_BAND + lr * 272 + cb + 16);
        af[3] = *(uint32_t*)(sm + OFF_BAND + (lr + 8) * 272 + cb + 16);
#pragma unroll
        for (int nc = 0; nc < 8; ++nc) {
            int base = (nc * 8 + tq) * 272 + cb;
            uint32_t b0 = *(uint32_t*)(sm + OFF_WRVT + base);
            uint32_t b1 = *(uint32_t*)(sm + OFF_WRVT + base + 16);
            mma16816(ctx[nc], af, b0, b1);
        }
    }

    // ---- reduce rowsums / edge-p across the quad, write out ----
    rs0 += __shfl_xor_sync(0xffffffffu, rs0, 1);
    rs0 += __shfl_xor_sync(0xffffffffu, rs0, 2);
    rs1 += __shfl_xor_sync(0xffffffffu, rs1, 1);
    rs1 += __shfl_xor_sync(0xffffffffu, rs1, 2);
    pe0 += __shfl_xor_sync(0xffffffffu, pe0, 1);
    pe0 += __shfl_xor_sync(0xffffffffu, pe0, 2);
    pe1 += __shfl_xor_sync(0xffffffffu, pe1, 1);
    pe1 += __shfl_xor_sync(0xffffffffu, pe1, 2);
    float inv0 = 1.0f / rs0, inv1 = 1.0f / rs1;
    const float* wrvE = Wrv + 128 * 64;
#pragma unroll
    for (int nc = 0; nc < 8; ++nc) {
        int d = nc * 8 + tr * 2;
        float2 o0, o1;
        o0.x = (ctx[nc][0] + pe0 * wrvE[d])     * inv0;
        o0.y = (ctx[nc][1] + pe0 * wrvE[d + 1]) * inv0;
        o1.x = (ctx[nc][2] + pe1 * wrvE[d])     * inv1;
        o1.y = (ctx[nc][3] + pe1 * wrvE[d + 1]) * inv1;
        *(float2*)(out + (size_t)(i0 + lr) * 1024 + hc + d)     = o0;
        *(float2*)(out + (size_t)(i0 + lr + 8) * 1024 + hc + d) = o1;
    }
}

// ---------------------------------------------------------------------------
extern "C" void kernel_launch(void* const* d_in, const int* in_sizes, int n_in,
                              void* d_out, int out_size)
{
    const float* X   = (const float*)d_in[0];
    const float* msk = (const float*)d_in[1];
    const float* Wq  = (const float*)d_in[2];
    const float* bq  = (const float*)d_in[3];
    const float* Wk  = (const float*)d_in[4];
    const float* bk  = (const float*)d_in[5];
    const float* Wv  = (const float*)d_in[6];
    const float* bv  = (const float*)d_in[7];
    const float* Wrk = (const float*)d_in[8];
    const float* Wrv = (const float*)d_in[9];
    float* out = (float*)d_out;

    cudaFuncSetAttribute(attn_mma_kernel,
                         cudaFuncAttributeMaxDynamicSharedMemorySize, ATT_SMEM);

    dim3 gGemm(16, 16, 3);
    qkv_gemm_kernel<<<gGemm, 256>>>(X, Wq, bq, Wk, bk, Wv, bv);

    dim3 gAttn(16, 16);   // 2048/128 i-tiles, 16 heads
    attn_mma_kernel<<<gAttn, 256, ATT_SMEM>>>(msk, Wrk, Wrv, out);
}

// round 5
// speedup vs baseline: 1.7550x; 1.1808x over previous
#include <cuda_runtime.h>
#include <cuda_bf16.h>
#include <cstdint>

// bf16 hi/lo split Q/K/V, written by the projection GEMM
__device__ __nv_bfloat16 g_Qh[2048 * 1024], g_Ql[2048 * 1024];
__device__ __nv_bfloat16 g_Kh[2048 * 1024], g_Kl[2048 * 1024];
__device__ __nv_bfloat16 g_Vh[2048 * 1024], g_Vl[2048 * 1024];

// ---------------- smem layout (bytes) for attention kernel ----------------
#define OFF_KH   0        /* [64][72] bf16, row stride 144B */
#define OFF_KL   9216
#define OFF_VTH  18432    /* [64][72] bf16 (V transposed)   */
#define OFF_VTL  27648
#define OFF_AK   36864    /* bf16 [128][132]                */
#define OFF_BAND 70656    /* bf16 [128][136]                */
#define OFF_MS   105472   /* 64 floats                      */
#define ATT_SMEM 105728
#define OFF_WRVT OFF_KH   /* overlay after mainloop: [64][136] = 17408B */

// ---------------- helpers ----------------
__device__ __forceinline__ void mma16816(float* c, const uint32_t* a,
                                         uint32_t b0, uint32_t b1) {
    asm volatile(
        "mma.sync.aligned.m16n8k16.row.col.f32.bf16.bf16.f32 "
        "{%0,%1,%2,%3}, {%4,%5,%6,%7}, {%8,%9}, {%0,%1,%2,%3};"
        : "+f"(c[0]), "+f"(c[1]), "+f"(c[2]), "+f"(c[3])
        : "r"(a[0]), "r"(a[1]), "r"(a[2]), "r"(a[3]), "r"(b0), "r"(b1));
}
__device__ __forceinline__ void split2u(float x, float y, uint32_t& h, uint32_t& l) {
    __nv_bfloat16 hx = __float2bfloat16(x), hy = __float2bfloat16(y);
    h = ((uint32_t)__bfloat16_as_ushort(hy) << 16) | __bfloat16_as_ushort(hx);
    __nv_bfloat16 lx = __float2bfloat16(x - __bfloat162float(hx));
    __nv_bfloat16 ly = __float2bfloat16(y - __bfloat162float(hy));
    l = ((uint32_t)__bfloat16_as_ushort(ly) << 16) | __bfloat16_as_ushort(lx);
}

// ---------------------------------------------------------------------------
// Kernel 1: SIMT QKV GEMM; epilogue writes bf16 hi/lo pairs.
// ---------------------------------------------------------------------------
__global__ __launch_bounds__(256, 4)
void qkv_gemm_kernel(const float* __restrict__ X,
                     const float* __restrict__ Wq, const float* __restrict__ bq,
                     const float* __restrict__ Wk, const float* __restrict__ bk,
                     const float* __restrict__ Wv, const float* __restrict__ bv)
{
    __shared__ float As[16][128];
    __shared__ float Bs[16][64];
    const float* W; const float* bias;
    __nv_bfloat16 *Gh, *Gl;
    if (blockIdx.z == 0)      { W = Wq; bias = bq; Gh = g_Qh; Gl = g_Ql; }
    else if (blockIdx.z == 1) { W = Wk; bias = bk; Gh = g_Kh; Gl = g_Kl; }
    else                      { W = Wv; bias = bv; Gh = g_Vh; Gl = g_Vl; }
    const int tid = threadIdx.x, tx = tid & 15, ty = tid >> 4;
    const int m0 = blockIdx.y * 128, n0 = blockIdx.x * 64;
    float acc[8][4];
#pragma unroll
    for (int r = 0; r < 8; ++r)
#pragma unroll
        for (int c = 0; c < 4; ++c) acc[r][c] = 0.f;
    for (int k0 = 0; k0 < 1024; k0 += 16) {
#pragma unroll
        for (int l = tid; l < 512; l += 256) {
            int row = l >> 2, kk = (l & 3) << 2;
            float4 v = *(const float4*)(X + (size_t)(m0 + row) * 1024 + k0 + kk);
            As[kk][row] = v.x; As[kk + 1][row] = v.y;
            As[kk + 2][row] = v.z; As[kk + 3][row] = v.w;
        }
        {
            int row = tid >> 4, c4 = (tid & 15) << 2;
            *(float4*)&Bs[row][c4] = *(const float4*)(W + (size_t)(k0 + row) * 1024 + n0 + c4);
        }
        __syncthreads();
#pragma unroll
        for (int k = 0; k < 16; ++k) {
            float4 b = *(float4*)&Bs[k][tx << 2];
            float4 a0 = *(float4*)&As[k][ty << 3];
            float4 a1 = *(float4*)&As[k][(ty << 3) + 4];
            float ar[8] = {a0.x, a0.y, a0.z, a0.w, a1.x, a1.y, a1.z, a1.w};
#pragma unroll
            for (int r = 0; r < 8; ++r) {
                acc[r][0] += ar[r] * b.x; acc[r][1] += ar[r] * b.y;
                acc[r][2] += ar[r] * b.z; acc[r][3] += ar[r] * b.w;
            }
        }
        __syncthreads();
    }
    float4 bb = *(const float4*)(bias + n0 + (tx << 2));
#pragma unroll
    for (int r = 0; r < 8; ++r) {
        int row = m0 + (ty << 3) + r;
        float v0 = acc[r][0] + bb.x, v1 = acc[r][1] + bb.y;
        float v2 = acc[r][2] + bb.z, v3 = acc[r][3] + bb.w;
        uint32_t h0, l0, h1, l1;
        split2u(v0, v1, h0, l0); split2u(v2, v3, h1, l1);
        uint2 H = {h0, h1}, L = {l0, l1};
        size_t off = (size_t)row * 1024 + n0 + (tx << 2);
        *(uint2*)(Gh + off) = H;
        *(uint2*)(Gl + off) = L;
    }
}

// ---------------------------------------------------------------------------
// Kernel 2: HMMA flash attention. 2 CTAs/SM (105.7KB smem, <=128 regs).
// Block = (i-tile of 128 rows, head). 256 threads = 8 warps x 16 rows.
// ---------------------------------------------------------------------------
__global__ __launch_bounds__(256, 2)
void attn_mma_kernel(const float* __restrict__ mask,
                     const float* __restrict__ Wrk,   // [64][129]
                     const float* __restrict__ Wrv,   // [129][64]
                     float* __restrict__ out)
{
    extern __shared__ __align__(16) char sm[];
    const int tid  = threadIdx.x;
    const int warp = tid >> 5, lane = tid & 31;
    const int tq = lane >> 2, tr = lane & 3;
    const int lr = warp * 16 + tq;
    const int i0 = blockIdx.x * 128, hc = blockIdx.y * 64;

    __nv_bfloat16* AK = (__nv_bfloat16*)(sm + OFF_AK);
    float* MS = (float*)(sm + OFF_MS);

    // ---- stage WrkT (hi only) into KH (w 0..63) / KL (w 64..127), [w][72] ----
    for (int l = tid; l < 1024; l += 256) {
        int w = l >> 4, dg = (l & 15) << 2;
        uint32_t a0, a1, b0, b1, t;
        split2u(Wrk[(dg + 0) * 129 + w],      Wrk[(dg + 1) * 129 + w],      a0, t);
        split2u(Wrk[(dg + 2) * 129 + w],      Wrk[(dg + 3) * 129 + w],      a1, t);
        split2u(Wrk[(dg + 0) * 129 + w + 64], Wrk[(dg + 1) * 129 + w + 64], b0, t);
        split2u(Wrk[(dg + 2) * 129 + w + 64], Wrk[(dg + 3) * 129 + w + 64], b1, t);
        uint2 A = {a0, a1}, B = {b0, b1};
        *(uint2*)(sm + OFF_KH + w * 144 + dg * 2) = A;
        *(uint2*)(sm + OFF_KL + w * 144 + dg * 2) = B;
    }
    // ---- zero band ----
    for (int l = tid; l < 8704; l += 256) ((uint32_t*)(sm + OFF_BAND))[l] = 0;
    // ---- edge bias column ak[:,128] from (hi+lo) Q ----
    if (tid < 128) {
        float s = 0.f;
        const __nv_bfloat16* qh_ = g_Qh + (size_t)(i0 + tid) * 1024 + hc;
        const __nv_bfloat16* ql_ = g_Ql + (size_t)(i0 + tid) * 1024 + hc;
#pragma unroll 8
        for (int d = 0; d < 64; ++d) {
            float q = __bfloat162float(qh_[d]) + __bfloat162float(ql_[d]);
            s += q * Wrk[d * 129 + 128];
        }
        AK[tid * 132 + 128] = __float2bfloat16(s);
    }
    __syncthreads();

    // ---- Q fragments: direct from gmem (one-time) ----
    uint32_t qh[4][4], ql[4][4];
#pragma unroll
    for (int kc = 0; kc < 4; ++kc) {
        size_t r0 = (size_t)(i0 + lr) * 1024 + hc + kc * 16 + tr * 2;
        size_t r1 = (size_t)(i0 + lr + 8) * 1024 + hc + kc * 16 + tr * 2;
        qh[kc][0] = *(const uint32_t*)(g_Qh + r0);
        qh[kc][1] = *(const uint32_t*)(g_Qh + r1);
        qh[kc][2] = *(const uint32_t*)(g_Qh + r0 + 8);
        qh[kc][3] = *(const uint32_t*)(g_Qh + r1 + 8);
        ql[kc][0] = *(const uint32_t*)(g_Ql + r0);
        ql[kc][1] = *(const uint32_t*)(g_Ql + r1);
        ql[kc][2] = *(const uint32_t*)(g_Ql + r0 + 8);
        ql[kc][3] = *(const uint32_t*)(g_Ql + r1 + 8);
    }

    // ---- ak = Q @ WrkT^T (hi), write bf16 table ----
#pragma unroll
    for (int half = 0; half < 2; ++half) {
        int KO = half ? OFF_KL : OFF_KH;
#pragma unroll
        for (int nc = 0; nc < 8; ++nc) {
            float c[4] = {0.f, 0.f, 0.f, 0.f};
#pragma unroll
            for (int kc = 0; kc < 4; ++kc) {
                int base = KO + (nc * 8 + tq) * 144 + (kc * 16 + tr * 2) * 2;
                uint32_t b0 = *(uint32_t*)(sm + base);
                uint32_t b1 = *(uint32_t*)(sm + base + 16);
                mma16816(c, qh[kc], b0, b1);
            }
            int w = half * 64 + nc * 8 + tr * 2;
            AK[lr * 132 + w]           = __float2bfloat16(c[0]);
            AK[lr * 132 + w + 1]       = __float2bfloat16(c[1]);
            AK[(lr + 8) * 132 + w]     = __float2bfloat16(c[2]);
            AK[(lr + 8) * 132 + w + 1] = __float2bfloat16(c[3]);
        }
    }
    __syncthreads();

    float ctx[8][4];
#pragma unroll
    for (int nc = 0; nc < 8; ++nc)
#pragma unroll
        for (int q = 0; q < 4; ++q) ctx[nc][q] = 0.f;
    float rs0 = 0.f, rs1 = 0.f, pe0 = 0.f, pe1 = 0.f;

    for (int jt = 0; jt < 32; ++jt) {
        const int j0 = jt * 64;
        // ---- stage K hi/lo: pure 16B copies ----
        for (int l = tid; l < 1024; l += 256) {
            int arr = l >> 9, idx = l & 511;
            int r = idx >> 3, ch = (idx & 7) << 3;     // 8 bf16 per 16B chunk
            const __nv_bfloat16* src =
                (arr ? g_Kl : g_Kh) + (size_t)(j0 + r) * 1024 + hc + ch;
            *(uint4*)(sm + (arr ? OFF_KL : OFF_KH) + r * 144 + ch * 2) =
                *(const uint4*)src;
        }
        // ---- stage V transposed hi/lo ----
        for (int l = tid; l < 1024; l += 256) {
            int j = l >> 4, dq = (l & 15) << 2;
            size_t off = (size_t)(j0 + j) * 1024 + hc + dq;
            uint2 hv = *(const uint2*)(g_Vh + off);
            uint2 lv = *(const uint2*)(g_Vl + off);
            __nv_bfloat16 h4[4], l4[4];
            *(uint2*)h4 = hv; *(uint2*)l4 = lv;
#pragma unroll
            for (int q = 0; q < 4; ++q) {
                *(__nv_bfloat16*)(sm + OFF_VTH + (dq + q) * 144 + j * 2) = h4[q];
                *(__nv_bfloat16*)(sm + OFF_VTL + (dq + q) * 144 + j * 2) = l4[q];
            }
        }
        if (tid < 64) MS[tid] = mask[j0 + tid];
        __syncthreads();

        // ---- S = Q K^T (3-term split) ----
        float c[8][4];
#pragma unroll
        for (int nc = 0; nc < 8; ++nc)
#pragma unroll
            for (int q = 0; q < 4; ++q) c[nc][q] = 0.f;
#pragma unroll
        for (int kc = 0; kc < 4; ++kc) {
#pragma unroll
            for (int nc = 0; nc < 8; ++nc) {
                int base = (nc * 8 + tq) * 144 + (kc * 16 + tr * 2) * 2;
                uint32_t bh0 = *(uint32_t*)(sm + OFF_KH + base);
                uint32_t bh1 = *(uint32_t*)(sm + OFF_KH + base + 16);
                uint32_t bl0 = *(uint32_t*)(sm + OFF_KL + base);
                uint32_t bl1 = *(uint32_t*)(sm + OFF_KL + base + 16);
                mma16816(c[nc], qh[kc], bh0, bh1);
                mma16816(c[nc], qh[kc], bl0, bl1);
                mma16816(c[nc], ql[kc], bh0, bh1);
            }
        }

        // ---- epilogue: bias + scale + mask + exp; band scatter ----
        const int sb0 = j0 - i0 + 64;
        const bool doBand = (sb0 >= -63 && sb0 <= 255);
#pragma unroll
        for (int nc = 0; nc < 8; ++nc) {
#pragma unroll
            for (int idx = 0; idx < 4; ++idx) {
                int lrr = lr + ((idx >> 1) << 3);
                int col = nc * 8 + tr * 2 + (idx & 1);
                float s = c[nc][idx];
                int w = sb0 + col - lrr;
                if (doBand && w >= 0 && w <= 128)
                    s += __bfloat162float(AK[lrr * 132 + w]);
                s = s * 0.125f + (1.0f - MS[col]) * (-3.4028235e38f);
                float e = __expf(s);
                if (idx < 2) rs0 += e; else rs1 += e;
                if (doBand) {
                    if (w >= 0 && w < 128)
                        *(__nv_bfloat16*)(sm + OFF_BAND + lrr * 272 + w * 2) =
                            __float2bfloat16(e);
                    else if (w == 128) { if (idx < 2) pe0 = e; else pe1 = e; }
                }
                c[nc][idx] = e;
            }
        }

        // ---- repack P as A-fragments (hi/lo) ----
        uint32_t ph[4][4], pl[4][4];
#pragma unroll
        for (int kc = 0; kc < 4; ++kc) {
            split2u(c[2 * kc][0],     c[2 * kc][1],     ph[kc][0], pl[kc][0]);
            split2u(c[2 * kc][2],     c[2 * kc][3],     ph[kc][1], pl[kc][1]);
            split2u(c[2 * kc + 1][0], c[2 * kc + 1][1], ph[kc][2], pl[kc][2]);
            split2u(c[2 * kc + 1][2], c[2 * kc + 1][3], ph[kc][3], pl[kc][3]);
        }

        // ---- ctx += P V (3-term split) ----
#pragma unroll
        for (int kc = 0; kc < 4; ++kc) {
#pragma unroll
            for (int nc = 0; nc < 8; ++nc) {
                int base = (nc * 8 + tq) * 144 + (kc * 16 + tr * 2) * 2;
                uint32_t vh0 = *(uint32_t*)(sm + OFF_VTH + base);
                uint32_t vh1 = *(uint32_t*)(sm + OFF_VTH + base + 16);
                uint32_t vl0 = *(uint32_t*)(sm + OFF_VTL + base);
                uint32_t vl1 = *(uint32_t*)(sm + OFF_VTL + base + 16);
                mma16816(ctx[nc], ph[kc], vh0, vh1);
                mma16816(ctx[nc], ph[kc], vl0, vl1);
                mma16816(ctx[nc], pl[kc], vh0, vh1);
            }
        }
        __syncthreads();
    }

    // ---- stage WrvT [d][136] (hi only), overlay on K buffers ----
    for (int l = tid; l < 8192; l += 256) {
        int d = l >> 7, w = l & 127;
        *(__nv_bfloat16*)(sm + OFF_WRVT + d * 272 + w * 2) =
            __float2bfloat16(Wrv[w * 64 + d]);
    }
    __syncthreads();

    // ---- ctx += band @ WrvT^T ----
#pragma unroll
    for (int kc = 0; kc < 8; ++kc) {
        int cb = (kc * 16 + tr * 2) * 2;
        uint32_t af[4];
        af[0] = *(uint32_t*)(sm + OFF_BAND + lr * 272 + cb);
        af[1] = *(uint32_t*)(sm + OFF_BAND + (lr + 8) * 272 + cb);
        af[2] = *(uint32_t*)(sm + OFF_BAND + lr * 272 + cb + 16);
        af[3] = *(uint32_t*)(sm + OFF_BAND + (lr + 8) * 272 + cb + 16);
#pragma unroll
        for (int nc = 0; nc < 8; ++nc) {
            int base = (nc * 8 + tq) * 272 + cb;
            uint32_t b0 = *(uint32_t*)(sm + OFF_WRVT + base);
            uint32_t b1 = *(uint32_t*)(sm + OFF_WRVT + base + 16);
            mma16816(ctx[nc], af, b0, b1);
        }
    }

    // ---- reduce rowsums / edge-p across the quad, write out ----
    rs0 += __shfl_xor_sync(0xffffffffu, rs0, 1);
    rs0 += __shfl_xor_sync(0xffffffffu, rs0, 2);
    rs1 += __shfl_xor_sync(0xffffffffu, rs1, 1);
    rs1 += __shfl_xor_sync(0xffffffffu, rs1, 2);
    pe0 += __shfl_xor_sync(0xffffffffu, pe0, 1);
    pe0 += __shfl_xor_sync(0xffffffffu, pe0, 2);
    pe1 += __shfl_xor_sync(0xffffffffu, pe1, 1);
    pe1 += __shfl_xor_sync(0xffffffffu, pe1, 2);
    float inv0 = 1.0f / rs0, inv1 = 1.0f / rs1;
    const float* wrvE = Wrv + 128 * 64;
#pragma unroll
    for (int nc = 0; nc < 8; ++nc) {
        int d = nc * 8 + tr * 2;
        float2 o0, o1;
        o0.x = (ctx[nc][0] + pe0 * wrvE[d])     * inv0;
        o0.y = (ctx[nc][1] + pe0 * wrvE[d + 1]) * inv0;
        o1.x = (ctx[nc][2] + pe1 * wrvE[d])     * inv1;
        o1.y = (ctx[nc][3] + pe1 * wrvE[d + 1]) * inv1;
        *(float2*)(out + (size_t)(i0 + lr) * 1024 + hc + d)     = o0;
        *(float2*)(out + (size_t)(i0 + lr + 8) * 1024 + hc + d) = o1;
    }
}

// ---------------------------------------------------------------------------
extern "C" void kernel_launch(void* const* d_in, const int* in_sizes, int n_in,
                              void* d_out, int out_size)
{
    const float* X   = (const float*)d_in[0];
    const float* msk = (const float*)d_in[1];
    const float* Wq  = (const float*)d_in[2];
    const float* bq  = (const float*)d_in[3];
    const float* Wk  = (const float*)d_in[4];
    const float* bk  = (const float*)d_in[5];
    const float* Wv  = (const float*)d_in[6];
    const float* bv  = (const float*)d_in[7];
    const float* Wrk = (const float*)d_in[8];
    const float* Wrv = (const float*)d_in[9];
    float* out = (float*)d_out;

    cudaFuncSetAttribute(attn_mma_kernel,
                         cudaFuncAttributeMaxDynamicSharedMemorySize, ATT_SMEM);

    dim3 gGemm(16, 16, 3);
    qkv_gemm_kernel<<<gGemm, 256>>>(X, Wq, bq, Wk, bk, Wv, bv);

    dim3 gAttn(16, 16);   // 2048/128 i-tiles, 16 heads
    attn_mma_kernel<<<gAttn, 256, ATT_SMEM>>>(msk, Wrk, Wrv, out);
}

// round 8
// speedup vs baseline: 2.5104x; 1.4304x over previous
#include <cuda_runtime.h>
#include <cuda_bf16.h>
#include <cstdint>

// bf16 hi/lo split buffers
__device__ __nv_bfloat16 g_Qh[2048 * 1024], g_Ql[2048 * 1024];
__device__ __nv_bfloat16 g_Kh[2048 * 1024], g_Kl[2048 * 1024];
__device__ __nv_bfloat16 g_Vh[2048 * 1024], g_Vl[2048 * 1024];
__device__ __nv_bfloat16 g_Xh[2048 * 1024], g_Xl[2048 * 1024];
__device__ __nv_bfloat16 g_WTh[3 * 1024 * 1024], g_WTl[3 * 1024 * 1024];

// ---------------- helpers ----------------
__device__ __forceinline__ void mma16816(float* c, const uint32_t* a,
                                         uint32_t b0, uint32_t b1) {
    asm volatile(
        "mma.sync.aligned.m16n8k16.row.col.f32.bf16.bf16.f32 "
        "{%0,%1,%2,%3}, {%4,%5,%6,%7}, {%8,%9}, {%0,%1,%2,%3};"
        : "+f"(c[0]), "+f"(c[1]), "+f"(c[2]), "+f"(c[3])
        : "r"(a[0]), "r"(a[1]), "r"(a[2]), "r"(a[3]), "r"(b0), "r"(b1));
}
__device__ __forceinline__ void split2u(float x, float y, uint32_t& h, uint32_t& l) {
    __nv_bfloat16 hx = __float2bfloat16(x), hy = __float2bfloat16(y);
    h = ((uint32_t)__bfloat16_as_ushort(hy) << 16) | __bfloat16_as_ushort(hx);
    __nv_bfloat16 lx = __float2bfloat16(x - __bfloat162float(hx));
    __nv_bfloat16 ly = __float2bfloat16(y - __bfloat162float(hy));
    l = ((uint32_t)__bfloat16_as_ushort(ly) << 16) | __bfloat16_as_ushort(lx);
}
__device__ __forceinline__ uint32_t smem_addr_u32(const void* p) {
    uint32_t a;
    asm("{ .reg .u64 t; cvta.to.shared.u64 t, %1; cvt.u32.u64 %0, t; }" : "=r"(a) : "l"(p));
    return a;
}

// ---------------------------------------------------------------------------
// Kernel 0a: X fp32 -> bf16 hi/lo
// ---------------------------------------------------------------------------
__global__ void convert_x_kernel(const float* __restrict__ X) {
    int row = blockIdx.x, col = threadIdx.x * 4;
    float4 v = *(const float4*)(X + (size_t)row * 1024 + col);
    uint32_t h0, l0, h1, l1;
    split2u(v.x, v.y, h0, l0); split2u(v.z, v.w, h1, l1);
    uint2 H = {h0, h1}, L = {l0, l1};
    *(uint2*)(g_Xh + (size_t)row * 1024 + col) = H;
    *(uint2*)(g_Xl + (size_t)row * 1024 + col) = L;
}

// ---------------------------------------------------------------------------
// Kernel 0b: W fp32 [k][n] -> transposed bf16 hi/lo [n][k]
// ---------------------------------------------------------------------------
__global__ void convert_w_kernel(const float* __restrict__ Wq,
                                 const float* __restrict__ Wk,
                                 const float* __restrict__ Wv) {
    __shared__ float t[32][33];
    const float* W = (blockIdx.z == 0) ? Wq : (blockIdx.z == 1) ? Wk : Wv;
    __nv_bfloat16* Th = g_WTh + (size_t)blockIdx.z * 1024 * 1024;
    __nv_bfloat16* Tl = g_WTl + (size_t)blockIdx.z * 1024 * 1024;
    int n0 = blockIdx.x * 32, k0 = blockIdx.y * 32;
    int tx = threadIdx.x, ty = threadIdx.y;
#pragma unroll
    for (int i = 0; i < 4; ++i)
        t[ty + 8 * i][tx] = W[(size_t)(k0 + ty + 8 * i) * 1024 + n0 + tx];
    __syncthreads();
#pragma unroll
    for (int i = 0; i < 4; ++i) {
        int n = n0 + ty + 8 * i;
        float v = t[tx][ty + 8 * i];
        __nv_bfloat16 hb = __float2bfloat16(v);
        __nv_bfloat16 lb = __float2bfloat16(v - __bfloat162float(hb));
        Th[(size_t)n * 1024 + k0 + tx] = hb;
        Tl[(size_t)n * 1024 + k0 + tx] = lb;
    }
}

// ---------------------------------------------------------------------------
// Kernel 1: HMMA QKV GEMM. Tile 128x128, BK=32, cp.async double-buffered.
// 8 warps: wm = warp&3 (32 rows), wn = warp>>2 (64 cols).
// ---------------------------------------------------------------------------
#define G_STRIDE 80      /* bytes per 32-bf16 row (+pad) */
#define G_ARR    10240   /* 128 * 80 */
#define G_STAGE  40960   /* 4 arrays */
#define GEMM_SMEM 81920

__global__ __launch_bounds__(256, 2)
void qkv_hmma_kernel(const float* __restrict__ bq,
                     const float* __restrict__ bk,
                     const float* __restrict__ bv)
{
    extern __shared__ __align__(16) char smG[];
    const int z = blockIdx.z;
    const __nv_bfloat16* Bh = g_WTh + (size_t)z * 1024 * 1024;
    const __nv_bfloat16* Bl = g_WTl + (size_t)z * 1024 * 1024;
    const float* bias = (z == 0) ? bq : (z == 1) ? bk : bv;
    __nv_bfloat16* Gh = (z == 0) ? g_Qh : (z == 1) ? g_Kh : g_Vh;
    __nv_bfloat16* Gl = (z == 0) ? g_Ql : (z == 1) ? g_Kl : g_Vl;

    const int tid = threadIdx.x;
    const int warp = tid >> 5, lane = tid & 31;
    const int q = lane >> 2, r = lane & 3;
    const int wm = warp & 3, wn = warp >> 2;
    const int m0 = blockIdx.y * 128, n0 = blockIdx.x * 128;

    float c[2][8][4];
#pragma unroll
    for (int mf = 0; mf < 2; ++mf)
#pragma unroll
        for (int nc = 0; nc < 8; ++nc)
#pragma unroll
            for (int i = 0; i < 4; ++i) c[mf][nc][i] = 0.f;

    // stage(buf, k0)
    auto stage = [&](int buf, int k0) {
        char* base = smG + buf * G_STAGE;
#pragma unroll
        for (int l = tid; l < 2048; l += 256) {
            int arr = l >> 9, idx = l & 511;
            int rr = idx >> 2, ch = idx & 3;
            const __nv_bfloat16* src;
            size_t off;
            if (arr < 2) {
                src = (arr == 0) ? g_Xh : g_Xl;
                off = (size_t)(m0 + rr) * 1024 + k0 + ch * 8;
            } else {
                src = (arr == 2) ? Bh : Bl;
                off = (size_t)(n0 + rr) * 1024 + k0 + ch * 8;
            }
            uint32_t dst = smem_addr_u32(base + arr * G_ARR + rr * G_STRIDE + ch * 16);
            asm volatile("cp.async.cg.shared.global [%0], [%1], 16;"
                         :: "r"(dst), "l"(src + off));
        }
    };

    stage(0, 0);
    asm volatile("cp.async.commit_group;");

    for (int kt = 0; kt < 32; ++kt) {
        if (kt + 1 < 32) {
            stage((kt + 1) & 1, (kt + 1) * 32);
            asm volatile("cp.async.commit_group;");
            asm volatile("cp.async.wait_group 1;");
        } else {
            asm volatile("cp.async.wait_group 0;");
        }
        __syncthreads();

        char* base = smG + (kt & 1) * G_STAGE;
        char* Ah = base;
        char* Al = base + G_ARR;
        char* Bsh = base + 2 * G_ARR;
        char* Bsl = base + 3 * G_ARR;

#pragma unroll
        for (int k16 = 0; k16 < 2; ++k16) {
            const int kb = k16 * 32 + r * 4;
            uint32_t ah[2][4], al[2][4];
#pragma unroll
            for (int mf = 0; mf < 2; ++mf) {
                int mrow = wm * 32 + mf * 16 + q;
                ah[mf][0] = *(uint32_t*)(Ah + mrow * G_STRIDE + kb);
                ah[mf][1] = *(uint32_t*)(Ah + (mrow + 8) * G_STRIDE + kb);
                ah[mf][2] = *(uint32_t*)(Ah + mrow * G_STRIDE + kb + 16);
                ah[mf][3] = *(uint32_t*)(Ah + (mrow + 8) * G_STRIDE + kb + 16);
                al[mf][0] = *(uint32_t*)(Al + mrow * G_STRIDE + kb);
                al[mf][1] = *(uint32_t*)(Al + (mrow + 8) * G_STRIDE + kb);
                al[mf][2] = *(uint32_t*)(Al + mrow * G_STRIDE + kb + 16);
                al[mf][3] = *(uint32_t*)(Al + (mrow + 8) * G_STRIDE + kb + 16);
            }
#pragma unroll
            for (int nc = 0; nc < 8; ++nc) {
                int nrow = wn * 64 + nc * 8 + q;
                uint32_t bh0 = *(uint32_t*)(Bsh + nrow * G_STRIDE + kb);
                uint32_t bh1 = *(uint32_t*)(Bsh + nrow * G_STRIDE + kb + 16);
                uint32_t bl0 = *(uint32_t*)(Bsl + nrow * G_STRIDE + kb);
                uint32_t bl1 = *(uint32_t*)(Bsl + nrow * G_STRIDE + kb + 16);
#pragma unroll
                for (int mf = 0; mf < 2; ++mf) {
                    mma16816(c[mf][nc], ah[mf], bh0, bh1);
                    mma16816(c[mf][nc], ah[mf], bl0, bl1);
                    mma16816(c[mf][nc], al[mf], bh0, bh1);
                }
            }
        }
        __syncthreads();
    }

    // epilogue: add bias, split to hi/lo
#pragma unroll
    for (int mf = 0; mf < 2; ++mf) {
        int row = m0 + wm * 32 + mf * 16 + q;
#pragma unroll
        for (int nc = 0; nc < 8; ++nc) {
            int col = n0 + wn * 64 + nc * 8 + r * 2;
            float b0 = bias[col], b1 = bias[col + 1];
            uint32_t h, l;
            split2u(c[mf][nc][0] + b0, c[mf][nc][1] + b1, h, l);
            *(uint32_t*)(Gh + (size_t)row * 1024 + col) = h;
            *(uint32_t*)(Gl + (size_t)row * 1024 + col) = l;
            split2u(c[mf][nc][2] + b0, c[mf][nc][3] + b1, h, l);
            *(uint32_t*)(Gh + (size_t)(row + 8) * 1024 + col) = h;
            *(uint32_t*)(Gl + (size_t)(row + 8) * 1024 + col) = l;
        }
    }
}

// ---------------------------------------------------------------------------
// Kernel 2: HMMA flash attention (unchanged from R5 — protect the win)
// ---------------------------------------------------------------------------
#define OFF_KH   0
#define OFF_KL   9216
#define OFF_VTH  18432
#define OFF_VTL  27648
#define OFF_AK   36864
#define OFF_BAND 70656
#define OFF_MS   105472
#define ATT_SMEM 105728
#define OFF_WRVT OFF_KH

__global__ __launch_bounds__(256, 2)
void attn_mma_kernel(const float* __restrict__ mask,
                     const float* __restrict__ Wrk,   // [64][129]
                     const float* __restrict__ Wrv,   // [129][64]
                     float* __restrict__ out)
{
    extern __shared__ __align__(16) char sm[];
    const int tid  = threadIdx.x;
    const int warp = tid >> 5, lane = tid & 31;
    const int tq = lane >> 2, tr = lane & 3;
    const int lr = warp * 16 + tq;
    const int i0 = blockIdx.x * 128, hc = blockIdx.y * 64;

    __nv_bfloat16* AK = (__nv_bfloat16*)(sm + OFF_AK);
    float* MS = (float*)(sm + OFF_MS);

    for (int l = tid; l < 1024; l += 256) {
        int w = l >> 4, dg = (l & 15) << 2;
        uint32_t a0, a1, b0, b1, t;
        split2u(Wrk[(dg + 0) * 129 + w],      Wrk[(dg + 1) * 129 + w],      a0, t);
        split2u(Wrk[(dg + 2) * 129 + w],      Wrk[(dg + 3) * 129 + w],      a1, t);
        split2u(Wrk[(dg + 0) * 129 + w + 64], Wrk[(dg + 1) * 129 + w + 64], b0, t);
        split2u(Wrk[(dg + 2) * 129 + w + 64], Wrk[(dg + 3) * 129 + w + 64], b1, t);
        uint2 A = {a0, a1}, B = {b0, b1};
        *(uint2*)(sm + OFF_KH + w * 144 + dg * 2) = A;
        *(uint2*)(sm + OFF_KL + w * 144 + dg * 2) = B;
    }
    for (int l = tid; l < 8704; l += 256) ((uint32_t*)(sm + OFF_BAND))[l] = 0;
    if (tid < 128) {
        float s = 0.f;
        const __nv_bfloat16* qh_ = g_Qh + (size_t)(i0 + tid) * 1024 + hc;
        const __nv_bfloat16* ql_ = g_Ql + (size_t)(i0 + tid) * 1024 + hc;
#pragma unroll 8
        for (int d = 0; d < 64; ++d) {
            float qv = __bfloat162float(qh_[d]) + __bfloat162float(ql_[d]);
            s += qv * Wrk[d * 129 + 128];
        }
        AK[tid * 132 + 128] = __float2bfloat16(s);
    }
    __syncthreads();

    uint32_t qh[4][4], ql[4][4];
#pragma unroll
    for (int kc = 0; kc < 4; ++kc) {
        size_t r0 = (size_t)(i0 + lr) * 1024 + hc + kc * 16 + tr * 2;
        size_t r1 = (size_t)(i0 + lr + 8) * 1024 + hc + kc * 16 + tr * 2;
        qh[kc][0] = *(const uint32_t*)(g_Qh + r0);
        qh[kc][1] = *(const uint32_t*)(g_Qh + r1);
        qh[kc][2] = *(const uint32_t*)(g_Qh + r0 + 8);
        qh[kc][3] = *(const uint32_t*)(g_Qh + r1 + 8);
        ql[kc][0] = *(const uint32_t*)(g_Ql + r0);
        ql[kc][1] = *(const uint32_t*)(g_Ql + r1);
        ql[kc][2] = *(const uint32_t*)(g_Ql + r0 + 8);
        ql[kc][3] = *(const uint32_t*)(g_Ql + r1 + 8);
    }

#pragma unroll
    for (int half = 0; half < 2; ++half) {
        int KO = half ? OFF_KL : OFF_KH;
#pragma unroll
        for (int nc = 0; nc < 8; ++nc) {
            float c[4] = {0.f, 0.f, 0.f, 0.f};
#pragma unroll
            for (int kc = 0; kc < 4; ++kc) {
                int base = KO + (nc * 8 + tq) * 144 + (kc * 16 + tr * 2) * 2;
                uint32_t b0 = *(uint32_t*)(sm + base);
                uint32_t b1 = *(uint32_t*)(sm + base + 16);
                mma16816(c, qh[kc], b0, b1);
            }
            int w = half * 64 + nc * 8 + tr * 2;
            AK[lr * 132 + w]           = __float2bfloat16(c[0]);
            AK[lr * 132 + w + 1]       = __float2bfloat16(c[1]);
            AK[(lr + 8) * 132 + w]     = __float2bfloat16(c[2]);
            AK[(lr + 8) * 132 + w + 1] = __float2bfloat16(c[3]);
        }
    }
    __syncthreads();

    float ctx[8][4];
#pragma unroll
    for (int nc = 0; nc < 8; ++nc)
#pragma unroll
        for (int qq = 0; qq < 4; ++qq) ctx[nc][qq] = 0.f;
    float rs0 = 0.f, rs1 = 0.f, pe0 = 0.f, pe1 = 0.f;

    for (int jt = 0; jt < 32; ++jt) {
        const int j0 = jt * 64;
        for (int l = tid; l < 1024; l += 256) {
            int arr = l >> 9, idx = l & 511;
            int r = idx >> 3, ch = (idx & 7) << 3;
            const __nv_bfloat16* src =
                (arr ? g_Kl : g_Kh) + (size_t)(j0 + r) * 1024 + hc + ch;
            *(uint4*)(sm + (arr ? OFF_KL : OFF_KH) + r * 144 + ch * 2) =
                *(const uint4*)src;
        }
        for (int l = tid; l < 1024; l += 256) {
            int j = l >> 4, dq = (l & 15) << 2;
            size_t off = (size_t)(j0 + j) * 1024 + hc + dq;
            uint2 hv = *(const uint2*)(g_Vh + off);
            uint2 lv = *(const uint2*)(g_Vl + off);
            __nv_bfloat16 h4[4], l4[4];
            *(uint2*)h4 = hv; *(uint2*)l4 = lv;
#pragma unroll
            for (int qq = 0; qq < 4; ++qq) {
                *(__nv_bfloat16*)(sm + OFF_VTH + (dq + qq) * 144 + j * 2) = h4[qq];
                *(__nv_bfloat16*)(sm + OFF_VTL + (dq + qq) * 144 + j * 2) = l4[qq];
            }
        }
        if (tid < 64) MS[tid] = mask[j0 + tid];
        __syncthreads();

        float c[8][4];
#pragma unroll
        for (int nc = 0; nc < 8; ++nc)
#pragma unroll
            for (int qq = 0; qq < 4; ++qq) c[nc][qq] = 0.f;
#pragma unroll
        for (int kc = 0; kc < 4; ++kc) {
#pragma unroll
            for (int nc = 0; nc < 8; ++nc) {
                int base = (nc * 8 + tq) * 144 + (kc * 16 + tr * 2) * 2;
                uint32_t bh0 = *(uint32_t*)(sm + OFF_KH + base);
                uint32_t bh1 = *(uint32_t*)(sm + OFF_KH + base + 16);
                uint32_t bl0 = *(uint32_t*)(sm + OFF_KL + base);
                uint32_t bl1 = *(uint32_t*)(sm + OFF_KL + base + 16);
                mma16816(c[nc], qh[kc], bh0, bh1);
                mma16816(c[nc], qh[kc], bl0, bl1);
                mma16816(c[nc], ql[kc], bh0, bh1);
            }
        }

        const int sb0 = j0 - i0 + 64;
        const bool doBand = (sb0 >= -63 && sb0 <= 255);
#pragma unroll
        for (int nc = 0; nc < 8; ++nc) {
#pragma unroll
            for (int idx = 0; idx < 4; ++idx) {
                int lrr = lr + ((idx >> 1) << 3);
                int col = nc * 8 + tr * 2 + (idx & 1);
                float s = c[nc][idx];
                int w = sb0 + col - lrr;
                if (doBand && w >= 0 && w <= 128)
                    s += __bfloat162float(AK[lrr * 132 + w]);
                s = s * 0.125f + (1.0f - MS[col]) * (-3.4028235e38f);
                float e = __expf(s);
                if (idx < 2) rs0 += e; else rs1 += e;
                if (doBand) {
                    if (w >= 0 && w < 128)
                        *(__nv_bfloat16*)(sm + OFF_BAND + lrr * 272 + w * 2) =
                            __float2bfloat16(e);
                    else if (w == 128) { if (idx < 2) pe0 = e; else pe1 = e; }
                }
                c[nc][idx] = e;
            }
        }

        uint32_t ph[4][4], pl[4][4];
#pragma unroll
        for (int kc = 0; kc < 4; ++kc) {
            split2u(c[2 * kc][0],     c[2 * kc][1],     ph[kc][0], pl[kc][0]);
            split2u(c[2 * kc][2],     c[2 * kc][3],     ph[kc][1], pl[kc][1]);
            split2u(c[2 * kc + 1][0], c[2 * kc + 1][1], ph[kc][2], pl[kc][2]);
            split2u(c[2 * kc + 1][2], c[2 * kc + 1][3], ph[kc][3], pl[kc][3]);
        }

#pragma unroll
        for (int kc = 0; kc < 4; ++kc) {
#pragma unroll
            for (int nc = 0; nc < 8; ++nc) {
                int base = (nc * 8 + tq) * 144 + (kc * 16 + tr * 2) * 2;
                uint32_t vh0 = *(uint32_t*)(sm + OFF_VTH + base);
                uint32_t vh1 = *(uint32_t*)(sm + OFF_VTH + base + 16);
                uint32_t vl0 = *(uint32_t*)(sm + OFF_VTL + base);
                uint32_t vl1 = *(uint32_t*)(sm + OFF_VTL + base + 16);
                mma16816(ctx[nc], ph[kc], vh0, vh1);
                mma16816(ctx[nc], ph[kc], vl0, vl1);
                mma16816(ctx[nc], pl[kc], vh0, vh1);
            }
        }
        __syncthreads();
    }

    for (int l = tid; l < 8192; l += 256) {
        int d = l >> 7, w = l & 127;
        *(__nv_bfloat16*)(sm + OFF_WRVT + d * 272 + w * 2) =
            __float2bfloat16(Wrv[w * 64 + d]);
    }
    __syncthreads();

#pragma unroll
    for (int kc = 0; kc < 8; ++kc) {
        int cb = (kc * 16 + tr * 2) * 2;
        uint32_t af[4];
        af[0] = *(uint32_t*)(sm + OFF_BAND + lr * 272 + cb);
        af[1] = *(uint32_t*)(sm + OFF_BAND + (lr + 8) * 272 + cb);
        af[2] = *(uint32_t*)(sm + OFF_BAND + lr * 272 + cb + 16);
        af[3] = *(uint32_t*)(sm + OFF_BAND + (lr + 8) * 272 + cb + 16);
#pragma unroll
        for (int nc = 0; nc < 8; ++nc) {
            int base = (nc * 8 + tq) * 272 + cb;
            uint32_t b0 = *(uint32_t*)(sm + OFF_WRVT + base);
            uint32_t b1 = *(uint32_t*)(sm + OFF_WRVT + base + 16);
            mma16816(ctx[nc], af, b0, b1);
        }
    }

    rs0 += __shfl_xor_sync(0xffffffffu, rs0, 1);
    rs0 += __shfl_xor_sync(0xffffffffu, rs0, 2);
    rs1 += __shfl_xor_sync(0xffffffffu, rs1, 1);
    rs1 += __shfl_xor_sync(0xffffffffu, rs1, 2);
    pe0 += __shfl_xor_sync(0xffffffffu, pe0, 1);
    pe0 += __shfl_xor_sync(0xffffffffu, pe0, 2);
    pe1 += __shfl_xor_sync(0xffffffffu, pe1, 1);
    pe1 += __shfl_xor_sync(0xffffffffu, pe1, 2);
    float inv0 = 1.0f / rs0, inv1 = 1.0f / rs1;
    const float* wrvE = Wrv + 128 * 64;
#pragma unroll
    for (int nc = 0; nc < 8; ++nc) {
        int d = nc * 8 + tr * 2;
        float2 o0, o1;
        o0.x = (ctx[nc][0] + pe0 * wrvE[d])     * inv0;
        o0.y = (ctx[nc][1] + pe0 * wrvE[d + 1]) * inv0;
        o1.x = (ctx[nc][2] + pe1 * wrvE[d])     * inv1;
        o1.y = (ctx[nc][3] + pe1 * wrvE[d + 1]) * inv1;
        *(float2*)(out + (size_t)(i0 + lr) * 1024 + hc + d)     = o0;
        *(float2*)(out + (size_t)(i0 + lr + 8) * 1024 + hc + d) = o1;
    }
}

// ---------------------------------------------------------------------------
extern "C" void kernel_launch(void* const* d_in, const int* in_sizes, int n_in,
                              void* d_out, int out_size)
{
    const float* X   = (const float*)d_in[0];
    const float* msk = (const float*)d_in[1];
    const float* Wq  = (const float*)d_in[2];
    const float* bq  = (const float*)d_in[3];
    const float* Wk  = (const float*)d_in[4];
    const float* bk  = (const float*)d_in[5];
    const float* Wv  = (const float*)d_in[6];
    const float* bv  = (const float*)d_in[7];
    const float* Wrk = (const float*)d_in[8];
    const float* Wrv = (const float*)d_in[9];
    float* out = (float*)d_out;

    cudaFuncSetAttribute(qkv_hmma_kernel,
                         cudaFuncAttributeMaxDynamicSharedMemorySize, GEMM_SMEM);
    cudaFuncSetAttribute(attn_mma_kernel,
                         cudaFuncAttributeMaxDynamicSharedMemorySize, ATT_SMEM);

    convert_x_kernel<<<2048, 256>>>(X);
    convert_w_kernel<<<dim3(32, 32, 3), dim3(32, 8)>>>(Wq, Wk, Wv);
    qkv_hmma_kernel<<<dim3(8, 16, 3), 256, GEMM_SMEM>>>(bq, bk, bv);

    dim3 gAttn(16, 16);
    attn_mma_kernel<<<gAttn, 256, ATT_SMEM>>>(msk, Wrk, Wrv, out);
}

// round 9
// speedup vs baseline: 3.0921x; 1.2317x over previous
#include <cuda_runtime.h>
#include <cuda_bf16.h>
#include <cstdint>

// bf16 hi/lo split buffers
__device__ __nv_bfloat16 g_Qh[2048 * 1024], g_Ql[2048 * 1024];
__device__ __nv_bfloat16 g_Kh[2048 * 1024], g_Kl[2048 * 1024];
__device__ __nv_bfloat16 g_Vh[2048 * 1024], g_Vl[2048 * 1024];
__device__ __nv_bfloat16 g_VTh[1024 * 2048], g_VTl[1024 * 2048];  // V transposed [d][j]
__device__ __nv_bfloat16 g_Xh[2048 * 1024], g_Xl[2048 * 1024];
__device__ __nv_bfloat16 g_WTh[3 * 1024 * 1024], g_WTl[3 * 1024 * 1024];

// ---------------- helpers ----------------
__device__ __forceinline__ void mma16816(float* c, const uint32_t* a,
                                         uint32_t b0, uint32_t b1) {
    asm volatile(
        "mma.sync.aligned.m16n8k16.row.col.f32.bf16.bf16.f32 "
        "{%0,%1,%2,%3}, {%4,%5,%6,%7}, {%8,%9}, {%0,%1,%2,%3};"
        : "+f"(c[0]), "+f"(c[1]), "+f"(c[2]), "+f"(c[3])
        : "r"(a[0]), "r"(a[1]), "r"(a[2]), "r"(a[3]), "r"(b0), "r"(b1));
}
__device__ __forceinline__ void split2u(float x, float y, uint32_t& h, uint32_t& l) {
    __nv_bfloat16 hx = __float2bfloat16(x), hy = __float2bfloat16(y);
    h = ((uint32_t)__bfloat16_as_ushort(hy) << 16) | __bfloat16_as_ushort(hx);
    __nv_bfloat16 lx = __float2bfloat16(x - __bfloat162float(hx));
    __nv_bfloat16 ly = __float2bfloat16(y - __bfloat162float(hy));
    l = ((uint32_t)__bfloat16_as_ushort(ly) << 16) | __bfloat16_as_ushort(lx);
}
__device__ __forceinline__ uint32_t smem_addr_u32(const void* p) {
    uint32_t a;
    asm("{ .reg .u64 t; cvta.to.shared.u64 t, %1; cvt.u32.u64 %0, t; }" : "=r"(a) : "l"(p));
    return a;
}
#define CP_ASYNC16(dst, src) \
    asm volatile("cp.async.cg.shared.global [%0], [%1], 16;" :: "r"(dst), "l"(src))
#define CP_COMMIT() asm volatile("cp.async.commit_group;")
#define CP_WAIT(n)  asm volatile("cp.async.wait_group %0;" :: "n"(n))

// ---------------------------------------------------------------------------
// Kernel 0a: X fp32 -> bf16 hi/lo
// ---------------------------------------------------------------------------
__global__ void convert_x_kernel(const float* __restrict__ X) {
    int row = blockIdx.x, col = threadIdx.x * 4;
    float4 v = *(const float4*)(X + (size_t)row * 1024 + col);
    uint32_t h0, l0, h1, l1;
    split2u(v.x, v.y, h0, l0); split2u(v.z, v.w, h1, l1);
    uint2 H = {h0, h1}, L = {l0, l1};
    *(uint2*)(g_Xh + (size_t)row * 1024 + col) = H;
    *(uint2*)(g_Xl + (size_t)row * 1024 + col) = L;
}

// ---------------------------------------------------------------------------
// Kernel 0b: W fp32 [k][n] -> transposed bf16 hi/lo [n][k]
// ---------------------------------------------------------------------------
__global__ void convert_w_kernel(const float* __restrict__ Wq,
                                 const float* __restrict__ Wk,
                                 const float* __restrict__ Wv) {
    __shared__ float t[32][33];
    const float* W = (blockIdx.z == 0) ? Wq : (blockIdx.z == 1) ? Wk : Wv;
    __nv_bfloat16* Th = g_WTh + (size_t)blockIdx.z * 1024 * 1024;
    __nv_bfloat16* Tl = g_WTl + (size_t)blockIdx.z * 1024 * 1024;
    int n0 = blockIdx.x * 32, k0 = blockIdx.y * 32;
    int tx = threadIdx.x, ty = threadIdx.y;
#pragma unroll
    for (int i = 0; i < 4; ++i)
        t[ty + 8 * i][tx] = W[(size_t)(k0 + ty + 8 * i) * 1024 + n0 + tx];
    __syncthreads();
#pragma unroll
    for (int i = 0; i < 4; ++i) {
        int n = n0 + ty + 8 * i;
        float v = t[tx][ty + 8 * i];
        __nv_bfloat16 hb = __float2bfloat16(v);
        __nv_bfloat16 lb = __float2bfloat16(v - __bfloat162float(hb));
        Th[(size_t)n * 1024 + k0 + tx] = hb;
        Tl[(size_t)n * 1024 + k0 + tx] = lb;
    }
}

// ---------------------------------------------------------------------------
// Kernel 0c: V bf16 [j][d] -> VT bf16 [d][j]   (hi and lo via z)
// ---------------------------------------------------------------------------
__global__ void transpose_v_kernel() {
    __shared__ __nv_bfloat16 t[32][33];
    const __nv_bfloat16* src = blockIdx.z ? g_Vl : g_Vh;
    __nv_bfloat16* dst = blockIdx.z ? g_VTl : g_VTh;
    int j0 = blockIdx.x * 32, d0 = blockIdx.y * 32;
    int tx = threadIdx.x, ty = threadIdx.y;
#pragma unroll
    for (int i = 0; i < 4; ++i)
        t[ty + 8 * i][tx] = src[(size_t)(j0 + ty + 8 * i) * 1024 + d0 + tx];
    __syncthreads();
#pragma unroll
    for (int i = 0; i < 4; ++i)
        dst[(size_t)(d0 + ty + 8 * i) * 2048 + j0 + tx] = t[tx][ty + 8 * i];
}

// ---------------------------------------------------------------------------
// Kernel 1: HMMA QKV GEMM (unchanged from R8 — protect the win)
// ---------------------------------------------------------------------------
#define G_STRIDE 80
#define G_ARR    10240
#define G_STAGE  40960
#define GEMM_SMEM 81920

__global__ __launch_bounds__(256, 2)
void qkv_hmma_kernel(const float* __restrict__ bq,
                     const float* __restrict__ bk,
                     const float* __restrict__ bv)
{
    extern __shared__ __align__(16) char smG[];
    const int z = blockIdx.z;
    const __nv_bfloat16* Bh = g_WTh + (size_t)z * 1024 * 1024;
    const __nv_bfloat16* Bl = g_WTl + (size_t)z * 1024 * 1024;
    const float* bias = (z == 0) ? bq : (z == 1) ? bk : bv;
    __nv_bfloat16* Gh = (z == 0) ? g_Qh : (z == 1) ? g_Kh : g_Vh;
    __nv_bfloat16* Gl = (z == 0) ? g_Ql : (z == 1) ? g_Kl : g_Vl;

    const int tid = threadIdx.x;
    const int warp = tid >> 5, lane = tid & 31;
    const int q = lane >> 2, r = lane & 3;
    const int wm = warp & 3, wn = warp >> 2;
    const int m0 = blockIdx.y * 128, n0 = blockIdx.x * 128;

    float c[2][8][4];
#pragma unroll
    for (int mf = 0; mf < 2; ++mf)
#pragma unroll
        for (int nc = 0; nc < 8; ++nc)
#pragma unroll
            for (int i = 0; i < 4; ++i) c[mf][nc][i] = 0.f;

    auto stage = [&](int buf, int k0) {
        char* base = smG + buf * G_STAGE;
#pragma unroll
        for (int l = tid; l < 2048; l += 256) {
            int arr = l >> 9, idx = l & 511;
            int rr = idx >> 2, ch = idx & 3;
            const __nv_bfloat16* src;
            size_t off;
            if (arr < 2) {
                src = (arr == 0) ? g_Xh : g_Xl;
                off = (size_t)(m0 + rr) * 1024 + k0 + ch * 8;
            } else {
                src = (arr == 2) ? Bh : Bl;
                off = (size_t)(n0 + rr) * 1024 + k0 + ch * 8;
            }
            uint32_t dst = smem_addr_u32(base + arr * G_ARR + rr * G_STRIDE + ch * 16);
            CP_ASYNC16(dst, src + off);
        }
    };

    stage(0, 0);
    CP_COMMIT();

    for (int kt = 0; kt < 32; ++kt) {
        if (kt + 1 < 32) {
            stage((kt + 1) & 1, (kt + 1) * 32);
            CP_COMMIT();
            CP_WAIT(1);
        } else {
            CP_WAIT(0);
        }
        __syncthreads();

        char* base = smG + (kt & 1) * G_STAGE;
        char* Ah = base;
        char* Al = base + G_ARR;
        char* Bsh = base + 2 * G_ARR;
        char* Bsl = base + 3 * G_ARR;

#pragma unroll
        for (int k16 = 0; k16 < 2; ++k16) {
            const int kb = k16 * 32 + r * 4;
            uint32_t ah[2][4], al[2][4];
#pragma unroll
            for (int mf = 0; mf < 2; ++mf) {
                int mrow = wm * 32 + mf * 16 + q;
                ah[mf][0] = *(uint32_t*)(Ah + mrow * G_STRIDE + kb);
                ah[mf][1] = *(uint32_t*)(Ah + (mrow + 8) * G_STRIDE + kb);
                ah[mf][2] = *(uint32_t*)(Ah + mrow * G_STRIDE + kb + 16);
                ah[mf][3] = *(uint32_t*)(Ah + (mrow + 8) * G_STRIDE + kb + 16);
                al[mf][0] = *(uint32_t*)(Al + mrow * G_STRIDE + kb);
                al[mf][1] = *(uint32_t*)(Al + (mrow + 8) * G_STRIDE + kb);
                al[mf][2] = *(uint32_t*)(Al + mrow * G_STRIDE + kb + 16);
                al[mf][3] = *(uint32_t*)(Al + (mrow + 8) * G_STRIDE + kb + 16);
            }
#pragma unroll
            for (int nc = 0; nc < 8; ++nc) {
                int nrow = wn * 64 + nc * 8 + q;
                uint32_t bh0 = *(uint32_t*)(Bsh + nrow * G_STRIDE + kb);
                uint32_t bh1 = *(uint32_t*)(Bsh + nrow * G_STRIDE + kb + 16);
                uint32_t bl0 = *(uint32_t*)(Bsl + nrow * G_STRIDE + kb);
                uint32_t bl1 = *(uint32_t*)(Bsl + nrow * G_STRIDE + kb + 16);
#pragma unroll
                for (int mf = 0; mf < 2; ++mf) {
                    mma16816(c[mf][nc], ah[mf], bh0, bh1);
                    mma16816(c[mf][nc], ah[mf], bl0, bl1);
                    mma16816(c[mf][nc], al[mf], bh0, bh1);
                }
            }
        }
        __syncthreads();
    }

#pragma unroll
    for (int mf = 0; mf < 2; ++mf) {
        int row = m0 + wm * 32 + mf * 16 + q;
#pragma unroll
        for (int nc = 0; nc < 8; ++nc) {
            int col = n0 + wn * 64 + nc * 8 + r * 2;
            float b0 = bias[col], b1 = bias[col + 1];
            uint32_t h, l;
            split2u(c[mf][nc][0] + b0, c[mf][nc][1] + b1, h, l);
            *(uint32_t*)(Gh + (size_t)row * 1024 + col) = h;
            *(uint32_t*)(Gl + (size_t)row * 1024 + col) = l;
            split2u(c[mf][nc][2] + b0, c[mf][nc][3] + b1, h, l);
            *(uint32_t*)(Gh + (size_t)(row + 8) * 1024 + col) = h;
            *(uint32_t*)(Gl + (size_t)(row + 8) * 1024 + col) = l;
        }
    }
}

// ---------------------------------------------------------------------------
// Kernel 2: HMMA flash attention with cp.async software pipelining.
// K smem reused after S-MMA; V smem reused after PV-MMA (single buffers).
// ---------------------------------------------------------------------------
#define OFF_KH   0
#define OFF_KL   9216
#define OFF_VTH  18432
#define OFF_VTL  27648
#define OFF_AK   36864
#define OFF_BAND 70656
#define OFF_MS   105472
#define ATT_SMEM 105728
#define OFF_WRVT OFF_KH

__global__ __launch_bounds__(256, 2)
void attn_mma_kernel(const float* __restrict__ mask,
                     const float* __restrict__ Wrk,   // [64][129]
                     const float* __restrict__ Wrv,   // [129][64]
                     float* __restrict__ out)
{
    extern __shared__ __align__(16) char sm[];
    const int tid  = threadIdx.x;
    const int warp = tid >> 5, lane = tid & 31;
    const int tq = lane >> 2, tr = lane & 3;
    const int lr = warp * 16 + tq;
    const int i0 = blockIdx.x * 128, hc = blockIdx.y * 64;

    __nv_bfloat16* AK = (__nv_bfloat16*)(sm + OFF_AK);
    float* MS = (float*)(sm + OFF_MS);

    // ---- stage WrkT (hi) into KH/KL (regular stores, pre-pipeline) ----
    for (int l = tid; l < 1024; l += 256) {
        int w = l >> 4, dg = (l & 15) << 2;
        uint32_t a0, a1, b0, b1, t;
        split2u(Wrk[(dg + 0) * 129 + w],      Wrk[(dg + 1) * 129 + w],      a0, t);
        split2u(Wrk[(dg + 2) * 129 + w],      Wrk[(dg + 3) * 129 + w],      a1, t);
        split2u(Wrk[(dg + 0) * 129 + w + 64], Wrk[(dg + 1) * 129 + w + 64], b0, t);
        split2u(Wrk[(dg + 2) * 129 + w + 64], Wrk[(dg + 3) * 129 + w + 64], b1, t);
        uint2 A = {a0, a1}, B = {b0, b1};
        *(uint2*)(sm + OFF_KH + w * 144 + dg * 2) = A;
        *(uint2*)(sm + OFF_KL + w * 144 + dg * 2) = B;
    }
    for (int l = tid; l < 8704; l += 256) ((uint32_t*)(sm + OFF_BAND))[l] = 0;
    if (tid < 128) {
        float s = 0.f;
        const __nv_bfloat16* qh_ = g_Qh + (size_t)(i0 + tid) * 1024 + hc;
        const __nv_bfloat16* ql_ = g_Ql + (size_t)(i0 + tid) * 1024 + hc;
#pragma unroll 8
        for (int d = 0; d < 64; ++d) {
            float qv = __bfloat162float(qh_[d]) + __bfloat162float(ql_[d]);
            s += qv * Wrk[d * 129 + 128];
        }
        AK[tid * 132 + 128] = __float2bfloat16(s);
    }
    __syncthreads();

    // ---- Q fragments: direct from gmem (one-time) ----
    uint32_t qh[4][4], ql[4][4];
#pragma unroll
    for (int kc = 0; kc < 4; ++kc) {
        size_t r0 = (size_t)(i0 + lr) * 1024 + hc + kc * 16 + tr * 2;
        size_t r1 = (size_t)(i0 + lr + 8) * 1024 + hc + kc * 16 + tr * 2;
        qh[kc][0] = *(const uint32_t*)(g_Qh + r0);
        qh[kc][1] = *(const uint32_t*)(g_Qh + r1);
        qh[kc][2] = *(const uint32_t*)(g_Qh + r0 + 8);
        qh[kc][3] = *(const uint32_t*)(g_Qh + r1 + 8);
        ql[kc][0] = *(const uint32_t*)(g_Ql + r0);
        ql[kc][1] = *(const uint32_t*)(g_Ql + r1);
        ql[kc][2] = *(const uint32_t*)(g_Ql + r0 + 8);
        ql[kc][3] = *(const uint32_t*)(g_Ql + r1 + 8);
    }

    // ---- ak = Q @ WrkT^T (hi), write bf16 table ----
#pragma unroll
    for (int half = 0; half < 2; ++half) {
        int KO = half ? OFF_KL : OFF_KH;
#pragma unroll
        for (int nc = 0; nc < 8; ++nc) {
            float c[4] = {0.f, 0.f, 0.f, 0.f};
#pragma unroll
            for (int kc = 0; kc < 4; ++kc) {
                int base = KO + (nc * 8 + tq) * 144 + (kc * 16 + tr * 2) * 2;
                uint32_t b0 = *(uint32_t*)(sm + base);
                uint32_t b1 = *(uint32_t*)(sm + base + 16);
                mma16816(c, qh[kc], b0, b1);
            }
            int w = half * 64 + nc * 8 + tr * 2;
            AK[lr * 132 + w]           = __float2bfloat16(c[0]);
            AK[lr * 132 + w + 1]       = __float2bfloat16(c[1]);
            AK[(lr + 8) * 132 + w]     = __float2bfloat16(c[2]);
            AK[(lr + 8) * 132 + w + 1] = __float2bfloat16(c[3]);
        }
    }
    __syncthreads();   // KH/KL dead -> safe for cp.async overwrite

    // ---- pipelined staging lambdas ----
    auto stageK = [&](int j0) {
#pragma unroll
        for (int l = tid; l < 1024; l += 256) {
            int arr = l >> 9, idx = l & 511;
            int r = idx >> 3, ch = idx & 7;
            const __nv_bfloat16* src =
                (arr ? g_Kl : g_Kh) + (size_t)(j0 + r) * 1024 + hc + ch * 8;
            uint32_t dst = smem_addr_u32(sm + (arr ? OFF_KL : OFF_KH) + r * 144 + ch * 16);
            CP_ASYNC16(dst, src);
        }
        if (tid < 16) {
            uint32_t dst = smem_addr_u32(sm + OFF_MS + tid * 16);
            CP_ASYNC16(dst, mask + j0 + tid * 4);
        }
    };
    auto stageV = [&](int j0) {
#pragma unroll
        for (int l = tid; l < 1024; l += 256) {
            int arr = l >> 9, idx = l & 511;
            int d = idx >> 3, ch = idx & 7;
            const __nv_bfloat16* src =
                (arr ? g_VTl : g_VTh) + (size_t)(hc + d) * 2048 + j0 + ch * 8;
            uint32_t dst = smem_addr_u32(sm + (arr ? OFF_VTL : OFF_VTH) + d * 144 + ch * 16);
            CP_ASYNC16(dst, src);
        }
    };

    stageK(0); CP_COMMIT();
    stageV(0); CP_COMMIT();

    float ctx[8][4];
#pragma unroll
    for (int nc = 0; nc < 8; ++nc)
#pragma unroll
        for (int qq = 0; qq < 4; ++qq) ctx[nc][qq] = 0.f;
    float rs0 = 0.f, rs1 = 0.f, pe0 = 0.f, pe1 = 0.f;

#pragma unroll 1
    for (int jt = 0; jt < 32; ++jt) {
        const int j0 = jt * 64;
        CP_WAIT(1);              // K(jt)+mask ready (V may be in flight)
        __syncthreads();

        // ---- S = Q K^T (3-term split) ----
        float c[8][4];
#pragma unroll
        for (int nc = 0; nc < 8; ++nc)
#pragma unroll
            for (int qq = 0; qq < 4; ++qq) c[nc][qq] = 0.f;
#pragma unroll
        for (int kc = 0; kc < 4; ++kc) {
#pragma unroll
            for (int nc = 0; nc < 8; ++nc) {
                int base = (nc * 8 + tq) * 144 + (kc * 16 + tr * 2) * 2;
                uint32_t bh0 = *(uint32_t*)(sm + OFF_KH + base);
                uint32_t bh1 = *(uint32_t*)(sm + OFF_KH + base + 16);
                uint32_t bl0 = *(uint32_t*)(sm + OFF_KL + base);
                uint32_t bl1 = *(uint32_t*)(sm + OFF_KL + base + 16);
                mma16816(c[nc], qh[kc], bh0, bh1);
                mma16816(c[nc], qh[kc], bl0, bl1);
                mma16816(c[nc], ql[kc], bh0, bh1);
            }
        }
        // snapshot mask before K/MS buffers get overwritten by prefetch
        float msv[8];
#pragma unroll
        for (int nc = 0; nc < 8; ++nc) msv[nc] = MS[nc * 8 + tr * 2];
        float msv1[8];
#pragma unroll
        for (int nc = 0; nc < 8; ++nc) msv1[nc] = MS[nc * 8 + tr * 2 + 1];
        __syncthreads();         // K + MS dead
        if (jt + 1 < 32) { stageK(j0 + 64); CP_COMMIT(); }

        // ---- epilogue: bias + scale + mask + exp2; band scatter ----
        const int sb0 = j0 - i0 + 64;
        const bool doBand = (sb0 >= -63 && sb0 <= 255);
#pragma unroll
        for (int nc = 0; nc < 8; ++nc) {
#pragma unroll
            for (int idx = 0; idx < 4; ++idx) {
                int lrr = lr + ((idx >> 1) << 3);
                int col = nc * 8 + tr * 2 + (idx & 1);
                float s = c[nc][idx];
                int w = sb0 + col - lrr;
                if (doBand && w >= 0 && w <= 128)
                    s += __bfloat162float(AK[lrr * 132 + w]);
                float m = (idx & 1) ? msv1[nc] : msv[nc];
                // e = exp(s/8 + (1-m)*MIN)  ==  exp2(s*0.125*log2e + (1-m)*(-big))
                float e = exp2f(fmaf(s, 0.18033688f, (1.0f - m) * (-1.0e30f)));
                if (idx < 2) rs0 += e; else rs1 += e;
                if (doBand) {
                    if (w >= 0 && w < 128)
                        *(__nv_bfloat16*)(sm + OFF_BAND + lrr * 272 + w * 2) =
                            __float2bfloat16(e);
                    else if (w == 128) { if (idx < 2) pe0 = e; else pe1 = e; }
                }
                c[nc][idx] = e;
            }
        }

        // ---- repack P as A-fragments (hi/lo) ----
        uint32_t ph[4][4], pl[4][4];
#pragma unroll
        for (int kc = 0; kc < 4; ++kc) {
            split2u(c[2 * kc][0],     c[2 * kc][1],     ph[kc][0], pl[kc][0]);
            split2u(c[2 * kc][2],     c[2 * kc][3],     ph[kc][1], pl[kc][1]);
            split2u(c[2 * kc + 1][0], c[2 * kc + 1][1], ph[kc][2], pl[kc][2]);
            split2u(c[2 * kc + 1][2], c[2 * kc + 1][3], ph[kc][3], pl[kc][3]);
        }

        if (jt + 1 < 32) { CP_WAIT(1); } else { CP_WAIT(0); }   // V(jt) ready
        __syncthreads();

        // ---- ctx += P V (3-term split) ----
#pragma unroll
        for (int kc = 0; kc < 4; ++kc) {
#pragma unroll
            for (int nc = 0; nc < 8; ++nc) {
                int base = (nc * 8 + tq) * 144 + (kc * 16 + tr * 2) * 2;
                uint32_t vh0 = *(uint32_t*)(sm + OFF_VTH + base);
                uint32_t vh1 = *(uint32_t*)(sm + OFF_VTH + base + 16);
                uint32_t vl0 = *(uint32_t*)(sm + OFF_VTL + base);
                uint32_t vl1 = *(uint32_t*)(sm + OFF_VTL + base + 16);
                mma16816(ctx[nc], ph[kc], vh0, vh1);
                mma16816(ctx[nc], ph[kc], vl0, vl1);
                mma16816(ctx[nc], pl[kc], vh0, vh1);
            }
        }
        __syncthreads();         // V dead
        if (jt + 1 < 32) { stageV(j0 + 64); CP_COMMIT(); }
    }

    // ---- stage WrvT [d][136] (hi only), overlay on K buffers ----
    for (int l = tid; l < 8192; l += 256) {
        int d = l >> 7, w = l & 127;
        *(__nv_bfloat16*)(sm + OFF_WRVT + d * 272 + w * 2) =
            __float2bfloat16(Wrv[w * 64 + d]);
    }
    __syncthreads();

    // ---- ctx += band @ WrvT^T ----
#pragma unroll
    for (int kc = 0; kc < 8; ++kc) {
        int cb = (kc * 16 + tr * 2) * 2;
        uint32_t af[4];
        af[0] = *(uint32_t*)(sm + OFF_BAND + lr * 272 + cb);
        af[1] = *(uint32_t*)(sm + OFF_BAND + (lr + 8) * 272 + cb);
        af[2] = *(uint32_t*)(sm + OFF_BAND + lr * 272 + cb + 16);
        af[3] = *(uint32_t*)(sm + OFF_BAND + (lr + 8) * 272 + cb + 16);
#pragma unroll
        for (int nc = 0; nc < 8; ++nc) {
            int base = (nc * 8 + tq) * 272 + cb;
            uint32_t b0 = *(uint32_t*)(sm + OFF_WRVT + base);
            uint32_t b1 = *(uint32_t*)(sm + OFF_WRVT + base + 16);
            mma16816(ctx[nc], af, b0, b1);
        }
    }

    // ---- reduce rowsums / edge-p across the quad, write out ----
    rs0 += __shfl_xor_sync(0xffffffffu, rs0, 1);
    rs0 += __shfl_xor_sync(0xffffffffu, rs0, 2);
    rs1 += __shfl_xor_sync(0xffffffffu, rs1, 1);
    rs1 += __shfl_xor_sync(0xffffffffu, rs1, 2);
    pe0 += __shfl_xor_sync(0xffffffffu, pe0, 1);
    pe0 += __shfl_xor_sync(0xffffffffu, pe0, 2);
    pe1 += __shfl_xor_sync(0xffffffffu, pe1, 1);
    pe1 += __shfl_xor_sync(0xffffffffu, pe1, 2);
    float inv0 = 1.0f / rs0, inv1 = 1.0f / rs1;
    const float* wrvE = Wrv + 128 * 64;
#pragma unroll
    for (int nc = 0; nc < 8; ++nc) {
        int d = nc * 8 + tr * 2;
        float2 o0, o1;
        o0.x = (ctx[nc][0] + pe0 * wrvE[d])     * inv0;
        o0.y = (ctx[nc][1] + pe0 * wrvE[d + 1]) * inv0;
        o1.x = (ctx[nc][2] + pe1 * wrvE[d])     * inv1;
        o1.y = (ctx[nc][3] + pe1 * wrvE[d + 1]) * inv1;
        *(float2*)(out + (size_t)(i0 + lr) * 1024 + hc + d)     = o0;
        *(float2*)(out + (size_t)(i0 + lr + 8) * 1024 + hc + d) = o1;
    }
}

// ---------------------------------------------------------------------------
extern "C" void kernel_launch(void* const* d_in, const int* in_sizes, int n_in,
                              void* d_out, int out_size)
{
    const float* X   = (const float*)d_in[0];
    const float* msk = (const float*)d_in[1];
    const float* Wq  = (const float*)d_in[2];
    const float* bq  = (const float*)d_in[3];
    const float* Wk  = (const float*)d_in[4];
    const float* bk  = (const float*)d_in[5];
    const float* Wv  = (const float*)d_in[6];
    const float* bv  = (const float*)d_in[7];
    const float* Wrk = (const float*)d_in[8];
    const float* Wrv = (const float*)d_in[9];
    float* out = (float*)d_out;

    cudaFuncSetAttribute(qkv_hmma_kernel,
                         cudaFuncAttributeMaxDynamicSharedMemorySize, GEMM_SMEM);
    cudaFuncSetAttribute(attn_mma_kernel,
                         cudaFuncAttributeMaxDynamicSharedMemorySize, ATT_SMEM);

    convert_x_kernel<<<2048, 256>>>(X);
    convert_w_kernel<<<dim3(32, 32, 3), dim3(32, 8)>>>(Wq, Wk, Wv);
    qkv_hmma_kernel<<<dim3(8, 16, 3), 256, GEMM_SMEM>>>(bq, bk, bv);
    transpose_v_kernel<<<dim3(64, 32, 2), dim3(32, 8)>>>();

    dim3 gAttn(16, 16);
    attn_mma_kernel<<<gAttn, 256, ATT_SMEM>>>(msk, Wrk, Wrv, out);
}

// round 10
// speedup vs baseline: 3.2450x; 1.0494x over previous
#include <cuda_runtime.h>
#include <cuda_bf16.h>
#include <cstdint>

// bf16 hi/lo split buffers
__device__ __nv_bfloat16 g_Qh[2048 * 1024], g_Ql[2048 * 1024];
__device__ __nv_bfloat16 g_Kh[2048 * 1024], g_Kl[2048 * 1024];
__device__ __nv_bfloat16 g_Vh[2048 * 1024], g_Vl[2048 * 1024];
__device__ __nv_bfloat16 g_VTh[1024 * 2048], g_VTl[1024 * 2048];  // V transposed [d][j]
__device__ __nv_bfloat16 g_Xh[2048 * 1024], g_Xl[2048 * 1024];
__device__ __nv_bfloat16 g_WTh[3 * 1024 * 1024], g_WTl[3 * 1024 * 1024];

// ---------------- helpers ----------------
__device__ __forceinline__ void mma16816(float* c, const uint32_t* a,
                                         uint32_t b0, uint32_t b1) {
    asm volatile(
        "mma.sync.aligned.m16n8k16.row.col.f32.bf16.bf16.f32 "
        "{%0,%1,%2,%3}, {%4,%5,%6,%7}, {%8,%9}, {%0,%1,%2,%3};"
        : "+f"(c[0]), "+f"(c[1]), "+f"(c[2]), "+f"(c[3])
        : "r"(a[0]), "r"(a[1]), "r"(a[2]), "r"(a[3]), "r"(b0), "r"(b1));
}
// fast packed hi/lo split: 2 cvt.bf16x2 + 2 lop + 2 sub
__device__ __forceinline__ void split2u(float x, float y, uint32_t& h, uint32_t& l) {
    __nv_bfloat162 hb = __float22bfloat162_rn(make_float2(x, y));
    h = *(uint32_t*)&hb;
    float xh = __uint_as_float(h << 16);
    float yh = __uint_as_float(h & 0xffff0000u);
    __nv_bfloat162 lb = __float22bfloat162_rn(make_float2(x - xh, y - yh));
    l = *(uint32_t*)&lb;
}
__device__ __forceinline__ uint32_t smem_addr_u32(const void* p) {
    uint32_t a;
    asm("{ .reg .u64 t; cvta.to.shared.u64 t, %1; cvt.u32.u64 %0, t; }" : "=r"(a) : "l"(p));
    return a;
}
__device__ __forceinline__ void ldsm4(uint32_t addr, uint32_t& r0, uint32_t& r1,
                                      uint32_t& r2, uint32_t& r3) {
    asm volatile("ldmatrix.sync.aligned.m8n8.x4.shared.b16 {%0,%1,%2,%3}, [%4];"
                 : "=r"(r0), "=r"(r1), "=r"(r2), "=r"(r3) : "r"(addr));
}
#define CP_ASYNC16(dst, src) \
    asm volatile("cp.async.cg.shared.global [%0], [%1], 16;" :: "r"(dst), "l"(src))
#define CP_COMMIT() asm volatile("cp.async.commit_group;")
#define CP_WAIT(n)  asm volatile("cp.async.wait_group %0;" :: "n"(n))

// ---------------------------------------------------------------------------
// Kernel 0a: X fp32 -> bf16 hi/lo
// ---------------------------------------------------------------------------
__global__ void convert_x_kernel(const float* __restrict__ X) {
    int row = blockIdx.x, col = threadIdx.x * 4;
    float4 v = *(const float4*)(X + (size_t)row * 1024 + col);
    uint32_t h0, l0, h1, l1;
    split2u(v.x, v.y, h0, l0); split2u(v.z, v.w, h1, l1);
    uint2 H = {h0, h1}, L = {l0, l1};
    *(uint2*)(g_Xh + (size_t)row * 1024 + col) = H;
    *(uint2*)(g_Xl + (size_t)row * 1024 + col) = L;
}

// ---------------------------------------------------------------------------
// Kernel 0b: W fp32 [k][n] -> transposed bf16 hi/lo [n][k]
// ---------------------------------------------------------------------------
__global__ void convert_w_kernel(const float* __restrict__ Wq,
                                 const float* __restrict__ Wk,
                                 const float* __restrict__ Wv) {
    __shared__ float t[32][33];
    const float* W = (blockIdx.z == 0) ? Wq : (blockIdx.z == 1) ? Wk : Wv;
    __nv_bfloat16* Th = g_WTh + (size_t)blockIdx.z * 1024 * 1024;
    __nv_bfloat16* Tl = g_WTl + (size_t)blockIdx.z * 1024 * 1024;
    int n0 = blockIdx.x * 32, k0 = blockIdx.y * 32;
    int tx = threadIdx.x, ty = threadIdx.y;
#pragma unroll
    for (int i = 0; i < 4; ++i)
        t[ty + 8 * i][tx] = W[(size_t)(k0 + ty + 8 * i) * 1024 + n0 + tx];
    __syncthreads();
#pragma unroll
    for (int i = 0; i < 4; ++i) {
        int n = n0 + ty + 8 * i;
        float v = t[tx][ty + 8 * i];
        __nv_bfloat16 hb = __float2bfloat16(v);
        __nv_bfloat16 lb = __float2bfloat16(v - __bfloat162float(hb));
        Th[(size_t)n * 1024 + k0 + tx] = hb;
        Tl[(size_t)n * 1024 + k0 + tx] = lb;
    }
}

// ---------------------------------------------------------------------------
// Kernel 0c: V bf16 [j][d] -> VT bf16 [d][j]
// ---------------------------------------------------------------------------
__global__ void transpose_v_kernel() {
    __shared__ __nv_bfloat16 t[32][33];
    const __nv_bfloat16* src = blockIdx.z ? g_Vl : g_Vh;
    __nv_bfloat16* dst = blockIdx.z ? g_VTl : g_VTh;
    int j0 = blockIdx.x * 32, d0 = blockIdx.y * 32;
    int tx = threadIdx.x, ty = threadIdx.y;
#pragma unroll
    for (int i = 0; i < 4; ++i)
        t[ty + 8 * i][tx] = src[(size_t)(j0 + ty + 8 * i) * 1024 + d0 + tx];
    __syncthreads();
#pragma unroll
    for (int i = 0; i < 4; ++i)
        dst[(size_t)(d0 + ty + 8 * i) * 2048 + j0 + tx] = t[tx][ty + 8 * i];
}

// ---------------------------------------------------------------------------
// Kernel 1: HMMA QKV GEMM (structure unchanged from R8; faster split2u)
// ---------------------------------------------------------------------------
#define G_STRIDE 80
#define G_ARR    10240
#define G_STAGE  40960
#define GEMM_SMEM 81920

__global__ __launch_bounds__(256, 2)
void qkv_hmma_kernel(const float* __restrict__ bq,
                     const float* __restrict__ bk,
                     const float* __restrict__ bv)
{
    extern __shared__ __align__(16) char smG[];
    const int z = blockIdx.z;
    const __nv_bfloat16* Bh = g_WTh + (size_t)z * 1024 * 1024;
    const __nv_bfloat16* Bl = g_WTl + (size_t)z * 1024 * 1024;
    const float* bias = (z == 0) ? bq : (z == 1) ? bk : bv;
    __nv_bfloat16* Gh = (z == 0) ? g_Qh : (z == 1) ? g_Kh : g_Vh;
    __nv_bfloat16* Gl = (z == 0) ? g_Ql : (z == 1) ? g_Kl : g_Vl;

    const int tid = threadIdx.x;
    const int warp = tid >> 5, lane = tid & 31;
    const int q = lane >> 2, r = lane & 3;
    const int wm = warp & 3, wn = warp >> 2;
    const int m0 = blockIdx.y * 128, n0 = blockIdx.x * 128;

    float c[2][8][4];
#pragma unroll
    for (int mf = 0; mf < 2; ++mf)
#pragma unroll
        for (int nc = 0; nc < 8; ++nc)
#pragma unroll
            for (int i = 0; i < 4; ++i) c[mf][nc][i] = 0.f;

    auto stage = [&](int buf, int k0) {
        char* base = smG + buf * G_STAGE;
#pragma unroll
        for (int l = tid; l < 2048; l += 256) {
            int arr = l >> 9, idx = l & 511;
            int rr = idx >> 2, ch = idx & 3;
            const __nv_bfloat16* src;
            size_t off;
            if (arr < 2) {
                src = (arr == 0) ? g_Xh : g_Xl;
                off = (size_t)(m0 + rr) * 1024 + k0 + ch * 8;
            } else {
                src = (arr == 2) ? Bh : Bl;
                off = (size_t)(n0 + rr) * 1024 + k0 + ch * 8;
            }
            uint32_t dst = smem_addr_u32(base + arr * G_ARR + rr * G_STRIDE + ch * 16);
            CP_ASYNC16(dst, src + off);
        }
    };

    stage(0, 0);
    CP_COMMIT();

    for (int kt = 0; kt < 32; ++kt) {
        if (kt + 1 < 32) {
            stage((kt + 1) & 1, (kt + 1) * 32);
            CP_COMMIT();
            CP_WAIT(1);
        } else {
            CP_WAIT(0);
        }
        __syncthreads();

        char* base = smG + (kt & 1) * G_STAGE;
        char* Ah = base;
        char* Al = base + G_ARR;
        char* Bsh = base + 2 * G_ARR;
        char* Bsl = base + 3 * G_ARR;

#pragma unroll
        for (int k16 = 0; k16 < 2; ++k16) {
            const int kb = k16 * 32 + r * 4;
            uint32_t ah[2][4], al[2][4];
#pragma unroll
            for (int mf = 0; mf < 2; ++mf) {
                int mrow = wm * 32 + mf * 16 + q;
                ah[mf][0] = *(uint32_t*)(Ah + mrow * G_STRIDE + kb);
                ah[mf][1] = *(uint32_t*)(Ah + (mrow + 8) * G_STRIDE + kb);
                ah[mf][2] = *(uint32_t*)(Ah + mrow * G_STRIDE + kb + 16);
                ah[mf][3] = *(uint32_t*)(Ah + (mrow + 8) * G_STRIDE + kb + 16);
                al[mf][0] = *(uint32_t*)(Al + mrow * G_STRIDE + kb);
                al[mf][1] = *(uint32_t*)(Al + (mrow + 8) * G_STRIDE + kb);
                al[mf][2] = *(uint32_t*)(Al + mrow * G_STRIDE + kb + 16);
                al[mf][3] = *(uint32_t*)(Al + (mrow + 8) * G_STRIDE + kb + 16);
            }
#pragma unroll
            for (int nc = 0; nc < 8; ++nc) {
                int nrow = wn * 64 + nc * 8 + q;
                uint32_t bh0 = *(uint32_t*)(Bsh + nrow * G_STRIDE + kb);
                uint32_t bh1 = *(uint32_t*)(Bsh + nrow * G_STRIDE + kb + 16);
                uint32_t bl0 = *(uint32_t*)(Bsl + nrow * G_STRIDE + kb);
                uint32_t bl1 = *(uint32_t*)(Bsl + nrow * G_STRIDE + kb + 16);
#pragma unroll
                for (int mf = 0; mf < 2; ++mf) {
                    mma16816(c[mf][nc], ah[mf], bh0, bh1);
                    mma16816(c[mf][nc], ah[mf], bl0, bl1);
                    mma16816(c[mf][nc], al[mf], bh0, bh1);
                }
            }
        }
        __syncthreads();
    }

#pragma unroll
    for (int mf = 0; mf < 2; ++mf) {
        int row = m0 + wm * 32 + mf * 16 + q;
#pragma unroll
        for (int nc = 0; nc < 8; ++nc) {
            int col = n0 + wn * 64 + nc * 8 + r * 2;
            float b0 = bias[col], b1 = bias[col + 1];
            uint32_t h, l;
            split2u(c[mf][nc][0] + b0, c[mf][nc][1] + b1, h, l);
            *(uint32_t*)(Gh + (size_t)row * 1024 + col) = h;
            *(uint32_t*)(Gl + (size_t)row * 1024 + col) = l;
            split2u(c[mf][nc][2] + b0, c[mf][nc][3] + b1, h, l);
            *(uint32_t*)(Gh + (size_t)(row + 8) * 1024 + col) = h;
            *(uint32_t*)(Gl + (size_t)(row + 8) * 1024 + col) = l;
        }
    }
}

// ---------------------------------------------------------------------------
// Kernel 2: HMMA flash attention, cp.async pipelined + ldmatrix fragment loads
// ---------------------------------------------------------------------------
#define OFF_KH   0
#define OFF_KL   9216
#define OFF_VTH  18432
#define OFF_VTL  27648
#define OFF_AK   36864
#define OFF_BAND 70656
#define OFF_MS   105472
#define ATT_SMEM 105728
#define OFF_WRVT OFF_KH

__global__ __launch_bounds__(256, 2)
void attn_mma_kernel(const float* __restrict__ mask,
                     const float* __restrict__ Wrk,   // [64][129]
                     const float* __restrict__ Wrv,   // [129][64]
                     float* __restrict__ out)
{
    extern __shared__ __align__(16) char sm[];
    const int tid  = threadIdx.x;
    const int warp = tid >> 5, lane = tid & 31;
    const int tq = lane >> 2, tr = lane & 3;
    const int lr = warp * 16 + tq;
    const int i0 = blockIdx.x * 128, hc = blockIdx.y * 64;

    __nv_bfloat16* AK = (__nv_bfloat16*)(sm + OFF_AK);
    float* MS = (float*)(sm + OFF_MS);
    const uint32_t sb = smem_addr_u32(sm);
    // ldmatrix per-lane row offset for 144B-stride tiles:
    // lanes 0-7: rows 0-7, k+0 | 8-15: rows 0-7, k+16B | 16-23: rows 8-15 | 24-31: rows 8-15, +16B
    const uint32_t loff = ((lane & 7) + ((lane >> 1) & 8)) * 144 + ((lane & 8) << 1);
    const uint32_t loff272 = ((lane & 7) + ((lane >> 1) & 8)) * 272 + ((lane & 8) << 1);

    // ---- stage WrkT (hi) into KH/KL ----
    for (int l = tid; l < 1024; l += 256) {
        int w = l >> 4, dg = (l & 15) << 2;
        uint32_t a0, a1, b0, b1, t;
        split2u(Wrk[(dg + 0) * 129 + w],      Wrk[(dg + 1) * 129 + w],      a0, t);
        split2u(Wrk[(dg + 2) * 129 + w],      Wrk[(dg + 3) * 129 + w],      a1, t);
        split2u(Wrk[(dg + 0) * 129 + w + 64], Wrk[(dg + 1) * 129 + w + 64], b0, t);
        split2u(Wrk[(dg + 2) * 129 + w + 64], Wrk[(dg + 3) * 129 + w + 64], b1, t);
        uint2 A = {a0, a1}, B = {b0, b1};
        *(uint2*)(sm + OFF_KH + w * 144 + dg * 2) = A;
        *(uint2*)(sm + OFF_KL + w * 144 + dg * 2) = B;
    }
    for (int l = tid; l < 8704; l += 256) ((uint32_t*)(sm + OFF_BAND))[l] = 0;
    if (tid < 128) {
        float s = 0.f;
        const __nv_bfloat16* qh_ = g_Qh + (size_t)(i0 + tid) * 1024 + hc;
        const __nv_bfloat16* ql_ = g_Ql + (size_t)(i0 + tid) * 1024 + hc;
#pragma unroll 8
        for (int d = 0; d < 64; ++d) {
            float qv = __bfloat162float(qh_[d]) + __bfloat162float(ql_[d]);
            s += qv * Wrk[d * 129 + 128];
        }
        AK[tid * 132 + 128] = __float2bfloat16(s);
    }
    __syncthreads();

    // ---- Q fragments: direct from gmem (one-time) ----
    uint32_t qh[4][4], ql[4][4];
#pragma unroll
    for (int kc = 0; kc < 4; ++kc) {
        size_t r0 = (size_t)(i0 + lr) * 1024 + hc + kc * 16 + tr * 2;
        size_t r1 = (size_t)(i0 + lr + 8) * 1024 + hc + kc * 16 + tr * 2;
        qh[kc][0] = *(const uint32_t*)(g_Qh + r0);
        qh[kc][1] = *(const uint32_t*)(g_Qh + r1);
        qh[kc][2] = *(const uint32_t*)(g_Qh + r0 + 8);
        qh[kc][3] = *(const uint32_t*)(g_Qh + r1 + 8);
        ql[kc][0] = *(const uint32_t*)(g_Ql + r0);
        ql[kc][1] = *(const uint32_t*)(g_Ql + r1);
        ql[kc][2] = *(const uint32_t*)(g_Ql + r0 + 8);
        ql[kc][3] = *(const uint32_t*)(g_Ql + r1 + 8);
    }

    // ---- ak = Q @ WrkT^T (hi) via ldmatrix ----
#pragma unroll
    for (int half = 0; half < 2; ++half) {
        const uint32_t KO = sb + (half ? OFF_KL : OFF_KH);
#pragma unroll
        for (int g = 0; g < 4; ++g) {
            float ca[4] = {0.f, 0.f, 0.f, 0.f}, cb[4] = {0.f, 0.f, 0.f, 0.f};
#pragma unroll
            for (int kc = 0; kc < 4; ++kc) {
                uint32_t h0, h1, h2, h3;
                ldsm4(KO + g * 2304 + kc * 32 + loff, h0, h1, h2, h3);
                mma16816(ca, qh[kc], h0, h1);
                mma16816(cb, qh[kc], h2, h3);
            }
#pragma unroll
            for (int pp = 0; pp < 2; ++pp) {
                const float* cc = pp ? cb : ca;
                int w = half * 64 + (2 * g + pp) * 8 + tr * 2;
                AK[lr * 132 + w]           = __float2bfloat16(cc[0]);
                AK[lr * 132 + w + 1]       = __float2bfloat16(cc[1]);
                AK[(lr + 8) * 132 + w]     = __float2bfloat16(cc[2]);
                AK[(lr + 8) * 132 + w + 1] = __float2bfloat16(cc[3]);
            }
        }
    }
    __syncthreads();   // KH/KL dead -> safe for cp.async overwrite

    // ---- pipelined staging lambdas ----
    auto stageK = [&](int j0) {
#pragma unroll
        for (int l = tid; l < 1024; l += 256) {
            int arr = l >> 9, idx = l & 511;
            int r = idx >> 3, ch = idx & 7;
            const __nv_bfloat16* src =
                (arr ? g_Kl : g_Kh) + (size_t)(j0 + r) * 1024 + hc + ch * 8;
            uint32_t dst = smem_addr_u32(sm + (arr ? OFF_KL : OFF_KH) + r * 144 + ch * 16);
            CP_ASYNC16(dst, src);
        }
        if (tid < 16) {
            uint32_t dst = smem_addr_u32(sm + OFF_MS + tid * 16);
            CP_ASYNC16(dst, mask + j0 + tid * 4);
        }
    };
    auto stageV = [&](int j0) {
#pragma unroll
        for (int l = tid; l < 1024; l += 256) {
            int arr = l >> 9, idx = l & 511;
            int d = idx >> 3, ch = idx & 7;
            const __nv_bfloat16* src =
                (arr ? g_VTl : g_VTh) + (size_t)(hc + d) * 2048 + j0 + ch * 8;
            uint32_t dst = smem_addr_u32(sm + (arr ? OFF_VTL : OFF_VTH) + d * 144 + ch * 16);
            CP_ASYNC16(dst, src);
        }
    };

    stageK(0); CP_COMMIT();
    stageV(0); CP_COMMIT();

    float ctx[8][4];
#pragma unroll
    for (int nc = 0; nc < 8; ++nc)
#pragma unroll
        for (int qq = 0; qq < 4; ++qq) ctx[nc][qq] = 0.f;
    float rs0 = 0.f, rs1 = 0.f, pe0 = 0.f, pe1 = 0.f;

#pragma unroll 1
    for (int jt = 0; jt < 32; ++jt) {
        const int j0 = jt * 64;
        CP_WAIT(1);              // K(jt)+mask ready (V may be in flight)
        __syncthreads();

        // ---- S = Q K^T (3-term split) via ldmatrix ----
        float c[8][4];
#pragma unroll
        for (int nc = 0; nc < 8; ++nc)
#pragma unroll
            for (int qq = 0; qq < 4; ++qq) c[nc][qq] = 0.f;
#pragma unroll
        for (int kc = 0; kc < 4; ++kc) {
#pragma unroll
            for (int g = 0; g < 4; ++g) {
                uint32_t h0, h1, h2, h3, e0, e1, e2, e3;
                ldsm4(sb + OFF_KH + g * 2304 + kc * 32 + loff, h0, h1, h2, h3);
                ldsm4(sb + OFF_KL + g * 2304 + kc * 32 + loff, e0, e1, e2, e3);
                mma16816(c[2 * g],     qh[kc], h0, h1);
                mma16816(c[2 * g],     qh[kc], e0, e1);
                mma16816(c[2 * g],     ql[kc], h0, h1);
                mma16816(c[2 * g + 1], qh[kc], h2, h3);
                mma16816(c[2 * g + 1], qh[kc], e2, e3);
                mma16816(c[2 * g + 1], ql[kc], h2, h3);
            }
        }
        // snapshot mask before K/MS buffers get overwritten by prefetch
        float msv[8], msv1[8];
#pragma unroll
        for (int nc = 0; nc < 8; ++nc) msv[nc] = MS[nc * 8 + tr * 2];
#pragma unroll
        for (int nc = 0; nc < 8; ++nc) msv1[nc] = MS[nc * 8 + tr * 2 + 1];
        __syncthreads();         // K + MS dead
        if (jt + 1 < 32) { stageK(j0 + 64); CP_COMMIT(); }

        // ---- epilogue: bias + scale + mask + exp2; band scatter ----
        const int sb0 = j0 - i0 + 64;
        const bool doBand = (sb0 >= -63 && sb0 <= 255);
#pragma unroll
        for (int nc = 0; nc < 8; ++nc) {
#pragma unroll
            for (int idx = 0; idx < 4; ++idx) {
                int lrr = lr + ((idx >> 1) << 3);
                int col = nc * 8 + tr * 2 + (idx & 1);
                float s = c[nc][idx];
                int w = sb0 + col - lrr;
                if (doBand && w >= 0 && w <= 128)
                    s += __bfloat162float(AK[lrr * 132 + w]);
                float m = (idx & 1) ? msv1[nc] : msv[nc];
                float e = exp2f(fmaf(s, 0.18033688f, (1.0f - m) * (-1.0e30f)));
                if (idx < 2) rs0 += e; else rs1 += e;
                if (doBand) {
                    if (w >= 0 && w < 128)
                        *(__nv_bfloat16*)(sm + OFF_BAND + lrr * 272 + w * 2) =
                            __float2bfloat16(e);
                    else if (w == 128) { if (idx < 2) pe0 = e; else pe1 = e; }
                }
                c[nc][idx] = e;
            }
        }

        // ---- repack P as A-fragments (hi/lo) ----
        uint32_t ph[4][4], pl[4][4];
#pragma unroll
        for (int kc = 0; kc < 4; ++kc) {
            split2u(c[2 * kc][0],     c[2 * kc][1],     ph[kc][0], pl[kc][0]);
            split2u(c[2 * kc][2],     c[2 * kc][3],     ph[kc][1], pl[kc][1]);
            split2u(c[2 * kc + 1][0], c[2 * kc + 1][1], ph[kc][2], pl[kc][2]);
            split2u(c[2 * kc + 1][2], c[2 * kc + 1][3], ph[kc][3], pl[kc][3]);
        }

        if (jt + 1 < 32) { CP_WAIT(1); } else { CP_WAIT(0); }   // V(jt) ready
        __syncthreads();

        // ---- ctx += P V (3-term split) via ldmatrix ----
#pragma unroll
        for (int kc = 0; kc < 4; ++kc) {
#pragma unroll
            for (int g = 0; g < 4; ++g) {
                uint32_t h0, h1, h2, h3, e0, e1, e2, e3;
                ldsm4(sb + OFF_VTH + g * 2304 + kc * 32 + loff, h0, h1, h2, h3);
                ldsm4(sb + OFF_VTL + g * 2304 + kc * 32 + loff, e0, e1, e2, e3);
                mma16816(ctx[2 * g],     ph[kc], h0, h1);
                mma16816(ctx[2 * g],     ph[kc], e0, e1);
                mma16816(ctx[2 * g],     pl[kc], h0, h1);
                mma16816(ctx[2 * g + 1], ph[kc], h2, h3);
                mma16816(ctx[2 * g + 1], ph[kc], e2, e3);
                mma16816(ctx[2 * g + 1], pl[kc], h2, h3);
            }
        }
        __syncthreads();         // V dead
        if (jt + 1 < 32) { stageV(j0 + 64); CP_COMMIT(); }
    }

    // ---- stage WrvT [d][136] (hi only), overlay on K buffers ----
    for (int l = tid; l < 8192; l += 256) {
        int d = l >> 7, w = l & 127;
        *(__nv_bfloat16*)(sm + OFF_WRVT + d * 272 + w * 2) =
            __float2bfloat16(Wrv[w * 64 + d]);
    }
    __syncthreads();

    // ---- ctx += band @ WrvT^T (ldmatrix, 272B stride) ----
#pragma unroll
    for (int kc = 0; kc < 8; ++kc) {
        int cb = (kc * 16 + tr * 2) * 2;
        uint32_t af[4];
        af[0] = *(uint32_t*)(sm + OFF_BAND + lr * 272 + cb);
        af[1] = *(uint32_t*)(sm + OFF_BAND + (lr + 8) * 272 + cb);
        af[2] = *(uint32_t*)(sm + OFF_BAND + lr * 272 + cb + 16);
        af[3] = *(uint32_t*)(sm + OFF_BAND + (lr + 8) * 272 + cb + 16);
#pragma unroll
        for (int g = 0; g < 4; ++g) {
            uint32_t h0, h1, h2, h3;
            ldsm4(sb + OFF_WRVT + g * 16 * 272 + kc * 32 + loff272, h0, h1, h2, h3);
            mma16816(ctx[2 * g],     af, h0, h1);
            mma16816(ctx[2 * g + 1], af, h2, h3);
        }
    }

    // ---- reduce rowsums / edge-p across the quad, write out ----
    rs0 += __shfl_xor_sync(0xffffffffu, rs0, 1);
    rs0 += __shfl_xor_sync(0xffffffffu, rs0, 2);
    rs1 += __shfl_xor_sync(0xffffffffu, rs1, 1);
    rs1 += __shfl_xor_sync(0xffffffffu, rs1, 2);
    pe0 += __shfl_xor_sync(0xffffffffu, pe0, 1);
    pe0 += __shfl_xor_sync(0xffffffffu, pe0, 2);
    pe1 += __shfl_xor_sync(0xffffffffu, pe1, 1);
    pe1 += __shfl_xor_sync(0xffffffffu, pe1, 2);
    float inv0 = 1.0f / rs0, inv1 = 1.0f / rs1;
    const float* wrvE = Wrv + 128 * 64;
#pragma unroll
    for (int nc = 0; nc < 8; ++nc) {
        int d = nc * 8 + tr * 2;
        float2 o0, o1;
        o0.x = (ctx[nc][0] + pe0 * wrvE[d])     * inv0;
        o0.y = (ctx[nc][1] + pe0 * wrvE[d + 1]) * inv0;
        o1.x = (ctx[nc][2] + pe1 * wrvE[d])     * inv1;
        o1.y = (ctx[nc][3] + pe1 * wrvE[d + 1]) * inv1;
        *(float2*)(out + (size_t)(i0 + lr) * 1024 + hc + d)     = o0;
        *(float2*)(out + (size_t)(i0 + lr + 8) * 1024 + hc + d) = o1;
    }
}

// ---------------------------------------------------------------------------
extern "C" void kernel_launch(void* const* d_in, const int* in_sizes, int n_in,
                              void* d_out, int out_size)
{
    const float* X   = (const float*)d_in[0];
    const float* msk = (const float*)d_in[1];
    const float* Wq  = (const float*)d_in[2];
    const float* bq  = (const float*)d_in[3];
    const float* Wk  = (const float*)d_in[4];
    const float* bk  = (const float*)d_in[5];
    const float* Wv  = (const float*)d_in[6];
    const float* bv  = (const float*)d_in[7];
    const float* Wrk = (const float*)d_in[8];
    const float* Wrv = (const float*)d_in[9];
    float* out = (float*)d_out;

    cudaFuncSetAttribute(qkv_hmma_kernel,
                         cudaFuncAttributeMaxDynamicSharedMemorySize, GEMM_SMEM);
    cudaFuncSetAttribute(attn_mma_kernel,
                         cudaFuncAttributeMaxDynamicSharedMemorySize, ATT_SMEM);

    convert_x_kernel<<<2048, 256>>>(X);
    convert_w_kernel<<<dim3(32, 32, 3), dim3(32, 8)>>>(Wq, Wk, Wv);
    qkv_hmma_kernel<<<dim3(8, 16, 3), 256, GEMM_SMEM>>>(bq, bk, bv);
    transpose_v_kernel<<<dim3(64, 32, 2), dim3(32, 8)>>>();

    dim3 gAttn(16, 16);
    attn_mma_kernel<<<gAttn, 256, ATT_SMEM>>>(msk, Wrk, Wrv, out);
}